// round 1
// baseline (speedup 1.0000x reference)
#include <cuda_runtime.h>
#include <cuda_bf16.h>
#include <cstdint>

// Problem constants
#define B_   32
#define RES_ 56
#define C_   128
#define H_   4
#define HD_  32
#define WS_  7
#define NW_  8
#define NQ_  64
#define WA_  49
#define TOPK_ 64
#define KV_  128          // total keys per window = 64 (grid) + 64 (x1)
#define P_   3136         // RES*RES
#define M0_  (B_*P_)      // 100352 rows for the big GEMM
#define M1_  (B_*NQ_)     // 2048 rows for the x1 GEMM

// -------- scratch (device globals: no allocation allowed) --------
__device__ float g_qkv0[(size_t)M0_ * 384];          // 154 MB
__device__ float g_qkv1[(size_t)M1_ * 384];          // 3 MB
__device__ float g_rpb[(size_t)NQ_ * H_ * WA_ * KV_];// 6.4 MB
__device__ float g_attn_out[(size_t)M0_ * C_];       // 51 MB (b*NQ*WA rows x C)

// ============================================================
// SGEMM: C[M,N] = A[M,K] * B[N,K]^T + bias[N]   (both K-contiguous)
// K must be a multiple of 16, M,N multiples of 64.
// ============================================================
__global__ __launch_bounds__(256) void sgemm_nt_bias(
    const float* __restrict__ A, const float* __restrict__ Bm,
    const float* __restrict__ bias, float* __restrict__ C,
    int M, int N, int K)
{
    const int BM = 64, BN = 64, BK = 16;
    __shared__ float As[BK][BM];
    __shared__ float Bs[BK][BN];

    int tid = threadIdx.x;
    int m0 = blockIdx.x * BM;
    int n0 = blockIdx.y * BN;
    int tx = tid & 15;          // 0..15 -> 4 cols each
    int ty = tid >> 4;          // 0..15 -> 4 rows each

    int lr = tid >> 2;          // 0..63 row within tile
    int lc = (tid & 3) * 4;     // 0,4,8,12 col within BK

    float acc[4][4];
#pragma unroll
    for (int r = 0; r < 4; r++)
#pragma unroll
        for (int c = 0; c < 4; c++) acc[r][c] = 0.f;

    for (int k0 = 0; k0 < K; k0 += BK) {
        float4 a4 = *(const float4*)&A[(size_t)(m0 + lr) * K + k0 + lc];
        float4 b4 = *(const float4*)&Bm[(size_t)(n0 + lr) * K + k0 + lc];
        As[lc + 0][lr] = a4.x; As[lc + 1][lr] = a4.y;
        As[lc + 2][lr] = a4.z; As[lc + 3][lr] = a4.w;
        Bs[lc + 0][lr] = b4.x; Bs[lc + 1][lr] = b4.y;
        Bs[lc + 2][lr] = b4.z; Bs[lc + 3][lr] = b4.w;
        __syncthreads();

#pragma unroll
        for (int k = 0; k < BK; k++) {
            float4 av = *(const float4*)&As[k][ty * 4];
            float4 bv = *(const float4*)&Bs[k][tx * 4];
            float a[4] = {av.x, av.y, av.z, av.w};
            float b[4] = {bv.x, bv.y, bv.z, bv.w};
#pragma unroll
            for (int r = 0; r < 4; r++)
#pragma unroll
                for (int c = 0; c < 4; c++) acc[r][c] = fmaf(a[r], b[c], acc[r][c]);
        }
        __syncthreads();
    }

    float4 bb = *(const float4*)&bias[n0 + tx * 4];
#pragma unroll
    for (int r = 0; r < 4; r++) {
        float4 o;
        o.x = acc[r][0] + bb.x; o.y = acc[r][1] + bb.y;
        o.z = acc[r][2] + bb.z; o.w = acc[r][3] + bb.w;
        *(float4*)&C[(size_t)(m0 + ty * 4 + r) * N + n0 + tx * 4] = o;
    }
}

// ============================================================
// RPB MLP precompute (batch independent):
//   rpb[w][h][i][j] for j<64 from coords0, j>=64 from coords1
// ============================================================
__global__ void rpb_kernel(
    const float* __restrict__ coords0, const float* __restrict__ coords1,
    const float* __restrict__ w1a, const float* __restrict__ b1a,
    const float* __restrict__ w2a, const float* __restrict__ b2a,
    const float* __restrict__ w1b, const float* __restrict__ b1b,
    const float* __restrict__ w2b, const float* __restrict__ b2b,
    float* __restrict__ rpb)
{
    int t = blockIdx.x * blockDim.x + threadIdx.x;
    const int TOT = NQ_ * WA_ * KV_;
    if (t >= TOT) return;
    int j = t & 127;
    int i = (t >> 7) % WA_;
    int w = t / (KV_ * WA_);

    const float *co, *w1, *b1, *w2, *b2;
    int jj;
    if (j < TOPK_) { co = coords0; jj = j;          w1 = w1a; b1 = b1a; w2 = w2a; b2 = b2a; }
    else           { co = coords1; jj = j - TOPK_;  w1 = w1b; b1 = b1b; w2 = w2b; b2 = b2b; }

    size_t cbase = ((size_t)(w * WA_ + i) * TOPK_ + jj) * 2;
    float cy = co[cbase + 0];
    float cx = co[cbase + 1];

    float o0 = b2[0], o1 = b2[1], o2 = b2[2], o3 = b2[3];
#pragma unroll
    for (int tt = 0; tt < HD_; tt++) {
        float hsum = fmaxf(fmaf(w1[tt * 2], cy, fmaf(w1[tt * 2 + 1], cx, b1[tt])), 0.f);
        o0 = fmaf(w2[0 * HD_ + tt], hsum, o0);
        o1 = fmaf(w2[1 * HD_ + tt], hsum, o1);
        o2 = fmaf(w2[2 * HD_ + tt], hsum, o2);
        o3 = fmaf(w2[3 * HD_ + tt], hsum, o3);
    }
    size_t base = ((size_t)(w * H_) * WA_ + i) * KV_ + j;
    const size_t hstride = (size_t)WA_ * KV_;
    rpb[base + 0 * hstride] = o0;
    rpb[base + 1 * hstride] = o1;
    rpb[base + 2 * hstride] = o2;
    rpb[base + 3 * hstride] = o3;
}

// ============================================================
// Fused gather + QK^T + rpb + softmax + PV per (b, window, head)
// ============================================================
__global__ __launch_bounds__(256) void attn_kernel(
    const int* __restrict__ idx0, const int* __restrict__ idx1,
    const float* __restrict__ rpb,
    const float* __restrict__ qkv0, const float* __restrict__ qkv1,
    float* __restrict__ attn_out)
{
    const int w = blockIdx.x, h = blockIdx.y, b = blockIdx.z;
    const int tid = threadIdx.x;

    __shared__ float q_s[WA_ * HD_];        // 1568 f
    __shared__ float v_s[KV_ * HD_];        // 4096 f
    __shared__ float p_s[WA_ * 129];        // padded logits
    __shared__ float inv_s[WA_];

    // ---- load Q (windowed layout from qkv0 columns [0,128)) ----
    const int wy = w >> 3, wx = w & 7;
    for (int idx = tid; idx < WA_ * HD_; idx += 256) {
        int i = idx / HD_, d = idx % HD_;
        int iy = i / WS_, ix = i % WS_;
        int pos = (wy * WS_ + iy) * RES_ + wx * WS_ + ix;
        q_s[idx] = qkv0[((size_t)b * P_ + pos) * 384 + h * HD_ + d];
    }

    // ---- gather K (registers) and V (smem) for key j = tid%128 ----
    const int j = tid & 127;
    const float* basep;
    if (j < TOPK_) {
        int pos = idx0[w * TOPK_ + j];
        basep = qkv0 + ((size_t)b * P_ + pos) * 384;
    } else {
        int pos = idx1[w * TOPK_ + (j - TOPK_)];
        basep = qkv1 + ((size_t)b * NQ_ + pos) * 384;
    }
    const float* kp = basep + C_ + h * HD_;
    float kreg[HD_];
#pragma unroll
    for (int d4 = 0; d4 < HD_ / 4; d4++) {
        float4 kk = *(const float4*)(kp + d4 * 4);
        kreg[d4 * 4 + 0] = kk.x; kreg[d4 * 4 + 1] = kk.y;
        kreg[d4 * 4 + 2] = kk.z; kreg[d4 * 4 + 3] = kk.w;
    }
    if (tid < 128) {
        const float* vp = basep + 2 * C_ + h * HD_;
#pragma unroll
        for (int d4 = 0; d4 < HD_ / 4; d4++)
            *(float4*)&v_s[j * HD_ + d4 * 4] = *(const float4*)(vp + d4 * 4);
    }
    __syncthreads();

    // ---- QK^T * scale + rpb ----
    const float scale = 0.17677669529663687f; // 1/sqrt(32)
    const float* rpb_wh = rpb + ((size_t)(w * H_ + h) * WA_) * KV_;
    const int iBeg = (tid < 128) ? 0 : 25;
    const int iEnd = (tid < 128) ? 25 : WA_;
    for (int i = iBeg; i < iEnd; i++) {
        float acc = 0.f;
#pragma unroll
        for (int d = 0; d < HD_; d++) acc = fmaf(q_s[i * HD_ + d], kreg[d], acc);
        p_s[i * 129 + j] = fmaf(acc, scale, rpb_wh[i * KV_ + j]);
    }
    __syncthreads();

    // ---- softmax: one warp per row ----
    const int lane = tid & 31, wrp = tid >> 5;
    for (int i = wrp; i < WA_; i += 8) {
        float x0 = p_s[i * 129 + lane];
        float x1 = p_s[i * 129 + lane + 32];
        float x2 = p_s[i * 129 + lane + 64];
        float x3 = p_s[i * 129 + lane + 96];
        float m = fmaxf(fmaxf(x0, x1), fmaxf(x2, x3));
#pragma unroll
        for (int off = 16; off; off >>= 1) m = fmaxf(m, __shfl_xor_sync(0xffffffffu, m, off));
        float e0 = __expf(x0 - m), e1 = __expf(x1 - m);
        float e2 = __expf(x2 - m), e3 = __expf(x3 - m);
        float s = e0 + e1 + e2 + e3;
#pragma unroll
        for (int off = 16; off; off >>= 1) s += __shfl_xor_sync(0xffffffffu, s, off);
        p_s[i * 129 + lane] = e0;
        p_s[i * 129 + lane + 32] = e1;
        p_s[i * 129 + lane + 64] = e2;
        p_s[i * 129 + lane + 96] = e3;
        if (lane == 0) inv_s[i] = 1.f / s;
    }
    __syncthreads();

    // ---- PV: 196 threads, each (i, 8 d's) ----
    if (tid < WA_ * 4) {
        const int i = tid >> 2;
        const int d0 = (tid & 3) * 8;
        float acc[8];
#pragma unroll
        for (int u = 0; u < 8; u++) acc[u] = 0.f;
        for (int jj = 0; jj < KV_; jj++) {
            float p = p_s[i * 129 + jj];
            float4 va = *(const float4*)&v_s[jj * HD_ + d0];
            float4 vb = *(const float4*)&v_s[jj * HD_ + d0 + 4];
            acc[0] = fmaf(p, va.x, acc[0]); acc[1] = fmaf(p, va.y, acc[1]);
            acc[2] = fmaf(p, va.z, acc[2]); acc[3] = fmaf(p, va.w, acc[3]);
            acc[4] = fmaf(p, vb.x, acc[4]); acc[5] = fmaf(p, vb.y, acc[5]);
            acc[6] = fmaf(p, vb.z, acc[6]); acc[7] = fmaf(p, vb.w, acc[7]);
        }
        const float inv = inv_s[i];
        size_t ob = (((size_t)(b * NQ_ + w) * WA_) + i) * C_ + h * HD_ + d0;
        float4 r0, r1;
        r0.x = acc[0] * inv; r0.y = acc[1] * inv; r0.z = acc[2] * inv; r0.w = acc[3] * inv;
        r1.x = acc[4] * inv; r1.y = acc[5] * inv; r1.z = acc[6] * inv; r1.w = acc[7] * inv;
        *(float4*)&attn_out[ob] = r0;
        *(float4*)&attn_out[ob + 4] = r1;
    }
}

// ============================================================
// launch
// ============================================================
extern "C" void kernel_launch(void* const* d_in, const int* in_sizes, int n_in,
                              void* d_out, int out_size)
{
    const float* x0      = (const float*)d_in[0];
    const float* x1      = (const float*)d_in[1];
    const float* qkv_w   = (const float*)d_in[2];
    const float* qkv_b   = (const float*)d_in[3];
    const float* proj_w  = (const float*)d_in[4];
    const float* proj_b  = (const float*)d_in[5];
    const float* rpb0_w1 = (const float*)d_in[6];
    const float* rpb0_b1 = (const float*)d_in[7];
    const float* rpb0_w2 = (const float*)d_in[8];
    const float* rpb0_b2 = (const float*)d_in[9];
    const float* rpb1_w1 = (const float*)d_in[10];
    const float* rpb1_b1 = (const float*)d_in[11];
    const float* rpb1_w2 = (const float*)d_in[12];
    const float* rpb1_b2 = (const float*)d_in[13];
    const float* coords0 = (const float*)d_in[14];
    const float* coords1 = (const float*)d_in[15];
    const int*   idx0    = (const int*)d_in[16];
    const int*   idx1    = (const int*)d_in[17];
    float* out = (float*)d_out;

    float *qkv0, *qkv1, *rpb, *attn_out;
    cudaGetSymbolAddress((void**)&qkv0, g_qkv0);
    cudaGetSymbolAddress((void**)&qkv1, g_qkv1);
    cudaGetSymbolAddress((void**)&rpb, g_rpb);
    cudaGetSymbolAddress((void**)&attn_out, g_attn_out);

    // 1) QKV for x0: (100352 x 128) @ (384 x 128)^T
    sgemm_nt_bias<<<dim3(M0_ / 64, 384 / 64), 256>>>(x0, qkv_w, qkv_b, qkv0, M0_, 384, 128);
    // 2) QKV for x1: (2048 x 128) @ (384 x 128)^T
    sgemm_nt_bias<<<dim3(M1_ / 64, 384 / 64), 256>>>(x1, qkv_w, qkv_b, qkv1, M1_, 384, 128);
    // 3) RPB table (batch independent)
    rpb_kernel<<<(NQ_ * WA_ * KV_ + 255) / 256, 256>>>(
        coords0, coords1,
        rpb0_w1, rpb0_b1, rpb0_w2, rpb0_b2,
        rpb1_w1, rpb1_b1, rpb1_w2, rpb1_b2, rpb);
    // 4) fused attention
    attn_kernel<<<dim3(NQ_, H_, B_), 256>>>(idx0, idx1, rpb, qkv0, qkv1, attn_out);
    // 5) projection: (100352 x 128) @ (128 x 128)^T -> d_out
    sgemm_nt_bias<<<dim3(M0_ / 64, C_ / 64), 256>>>(attn_out, proj_w, proj_b, out, M0_, C_, 128);
}

// round 2
// speedup vs baseline: 1.3799x; 1.3799x over previous
#include <cuda_runtime.h>
#include <cuda_bf16.h>
#include <cstdint>
#include <cstring>

// Problem constants
#define B_   32
#define RES_ 56
#define C_   128
#define H_   4
#define HD_  32
#define WS_  7
#define NW_  8
#define NQ_  64
#define WA_  49
#define TOPK_ 64
#define KV_  128
#define P_   3136
#define M0_  (B_*P_)      // 100352
#define M1_  (B_*NQ_)     // 2048

// -------- scratch (device globals: no allocation allowed) --------
__device__ float g_qkv0[(size_t)M0_ * 384];
__device__ float g_qkv1[(size_t)M1_ * 384];
__device__ float g_rpb[(size_t)NQ_ * H_ * WA_ * KV_];
__device__ float g_attn_out[(size_t)M0_ * C_];

// ---------- helpers ----------
__device__ __forceinline__ uint32_t f2tf32(float f) {
    uint32_t r;
    asm("cvt.rna.tf32.f32 %0, %1;" : "=r"(r) : "f"(f));
    return r;
}
__device__ __forceinline__ void fma2(unsigned long long& d,
                                     unsigned long long a,
                                     unsigned long long b) {
    asm("fma.rn.f32x2 %0, %1, %2, %0;" : "+l"(d) : "l"(a), "l"(b));
}
__device__ __forceinline__ unsigned long long dup2(float p) {
    unsigned long long r;
    asm("mov.b64 %0, {%1,%1};" : "=l"(r) : "f"(p));
    return r;
}

// ============================================================
// TF32 tensor-core GEMM: C[M,N] = A[M,K] * B[N,K]^T + bias[N]
// BM=BN=128, BK=16, 8 warps, warp tile 64x32, mma m16n8k8.
// M % 128 == 0, N % 128 == 0, K % 16 == 0.
// ============================================================
__global__ __launch_bounds__(256) void gemm_tf32(
    const float* __restrict__ A, const float* __restrict__ Bm,
    const float* __restrict__ bias, float* __restrict__ C,
    int M, int N, int K)
{
    __shared__ uint32_t As[128][20];
    __shared__ uint32_t Bs[128][20];

    const int tid = threadIdx.x;
    const int m0 = blockIdx.x * 128;
    const int n0 = blockIdx.y * 128;
    const int warp = tid >> 5, lane = tid & 31;
    const int wm = (warp >> 2) * 64;   // 0 or 64
    const int wn = (warp & 3) * 32;    // 0,32,64,96
    const int r = lane >> 2;           // 0..7
    const int cI = lane & 3;           // 0..3

    float c[4][4][4];
#pragma unroll
    for (int mt = 0; mt < 4; mt++)
#pragma unroll
        for (int nt = 0; nt < 4; nt++)
#pragma unroll
            for (int f = 0; f < 4; f++) c[mt][nt][f] = 0.f;

    const int lr = tid >> 1;           // 0..127
    const int ls = (tid & 1) * 8;      // 0 or 8
    const float* Arow = A + (size_t)(m0 + lr) * K + ls;
    const float* Brow = Bm + (size_t)(n0 + lr) * K + ls;

    for (int k0 = 0; k0 < K; k0 += 16) {
        float4 a1 = *(const float4*)(Arow + k0);
        float4 a2 = *(const float4*)(Arow + k0 + 4);
        float4 b1 = *(const float4*)(Brow + k0);
        float4 b2 = *(const float4*)(Brow + k0 + 4);
        uint4 ua1 = {f2tf32(a1.x), f2tf32(a1.y), f2tf32(a1.z), f2tf32(a1.w)};
        uint4 ua2 = {f2tf32(a2.x), f2tf32(a2.y), f2tf32(a2.z), f2tf32(a2.w)};
        uint4 ub1 = {f2tf32(b1.x), f2tf32(b1.y), f2tf32(b1.z), f2tf32(b1.w)};
        uint4 ub2 = {f2tf32(b2.x), f2tf32(b2.y), f2tf32(b2.z), f2tf32(b2.w)};
        *(uint4*)&As[lr][ls]     = ua1;
        *(uint4*)&As[lr][ls + 4] = ua2;
        *(uint4*)&Bs[lr][ls]     = ub1;
        *(uint4*)&Bs[lr][ls + 4] = ub2;
        __syncthreads();

#pragma unroll
        for (int k8 = 0; k8 < 16; k8 += 8) {
            uint32_t a[4][4], b[4][2];
#pragma unroll
            for (int mt = 0; mt < 4; mt++) {
                const int mrow = wm + mt * 16 + r;
                a[mt][0] = As[mrow][k8 + cI];
                a[mt][1] = As[mrow + 8][k8 + cI];
                a[mt][2] = As[mrow][k8 + cI + 4];
                a[mt][3] = As[mrow + 8][k8 + cI + 4];
            }
#pragma unroll
            for (int nt = 0; nt < 4; nt++) {
                const int nrow = wn + nt * 8 + r;
                b[nt][0] = Bs[nrow][k8 + cI];
                b[nt][1] = Bs[nrow][k8 + cI + 4];
            }
#pragma unroll
            for (int mt = 0; mt < 4; mt++)
#pragma unroll
                for (int nt = 0; nt < 4; nt++) {
                    asm volatile(
                        "mma.sync.aligned.m16n8k8.row.col.f32.tf32.tf32.f32 "
                        "{%0,%1,%2,%3},{%4,%5,%6,%7},{%8,%9},{%0,%1,%2,%3};"
                        : "+f"(c[mt][nt][0]), "+f"(c[mt][nt][1]),
                          "+f"(c[mt][nt][2]), "+f"(c[mt][nt][3])
                        : "r"(a[mt][0]), "r"(a[mt][1]), "r"(a[mt][2]), "r"(a[mt][3]),
                          "r"(b[nt][0]), "r"(b[nt][1]));
                }
        }
        __syncthreads();
    }

    // epilogue
#pragma unroll
    for (int mt = 0; mt < 4; mt++) {
        const int row = m0 + wm + mt * 16 + r;
#pragma unroll
        for (int nt = 0; nt < 4; nt++) {
            const int col = n0 + wn + nt * 8 + cI * 2;
            float2 bb = *(const float2*)&bias[col];
            float2 o0 = {c[mt][nt][0] + bb.x, c[mt][nt][1] + bb.y};
            float2 o1 = {c[mt][nt][2] + bb.x, c[mt][nt][3] + bb.y};
            *(float2*)&C[(size_t)row * N + col]       = o0;
            *(float2*)&C[(size_t)(row + 8) * N + col] = o1;
        }
    }
}

// ============================================================
// RPB MLP precompute (batch independent)
// ============================================================
__global__ void rpb_kernel(
    const float* __restrict__ coords0, const float* __restrict__ coords1,
    const float* __restrict__ w1a, const float* __restrict__ b1a,
    const float* __restrict__ w2a, const float* __restrict__ b2a,
    const float* __restrict__ w1b, const float* __restrict__ b1b,
    const float* __restrict__ w2b, const float* __restrict__ b2b,
    float* __restrict__ rpb)
{
    int t = blockIdx.x * blockDim.x + threadIdx.x;
    const int TOT = NQ_ * WA_ * KV_;
    if (t >= TOT) return;
    int j = t & 127;
    int i = (t >> 7) % WA_;
    int w = t / (KV_ * WA_);

    const float *co, *w1, *b1, *w2, *b2;
    int jj;
    if (j < TOPK_) { co = coords0; jj = j;          w1 = w1a; b1 = b1a; w2 = w2a; b2 = b2a; }
    else           { co = coords1; jj = j - TOPK_;  w1 = w1b; b1 = b1b; w2 = w2b; b2 = b2b; }

    size_t cbase = ((size_t)(w * WA_ + i) * TOPK_ + jj) * 2;
    float cy = co[cbase + 0];
    float cx = co[cbase + 1];

    float o0 = b2[0], o1 = b2[1], o2 = b2[2], o3 = b2[3];
#pragma unroll
    for (int tt = 0; tt < HD_; tt++) {
        float hsum = fmaxf(fmaf(w1[tt * 2], cy, fmaf(w1[tt * 2 + 1], cx, b1[tt])), 0.f);
        o0 = fmaf(w2[0 * HD_ + tt], hsum, o0);
        o1 = fmaf(w2[1 * HD_ + tt], hsum, o1);
        o2 = fmaf(w2[2 * HD_ + tt], hsum, o2);
        o3 = fmaf(w2[3 * HD_ + tt], hsum, o3);
    }
    size_t base = ((size_t)(w * H_) * WA_ + i) * KV_ + j;
    const size_t hstride = (size_t)WA_ * KV_;
    rpb[base + 0 * hstride] = o0;
    rpb[base + 1 * hstride] = o1;
    rpb[base + 2 * hstride] = o2;
    rpb[base + 3 * hstride] = o3;
}

// ============================================================
// Fused gather + QK^T + rpb + softmax + PV per (b, window, head)
// vectorized LDS (128-bit) + packed f32x2 FMA
// ============================================================
__global__ __launch_bounds__(256) void attn_kernel(
    const int* __restrict__ idx0, const int* __restrict__ idx1,
    const float* __restrict__ rpb,
    const float* __restrict__ qkv0, const float* __restrict__ qkv1,
    float* __restrict__ attn_out)
{
    const int w = blockIdx.x, h = blockIdx.y, b = blockIdx.z;
    const int tid = threadIdx.x;

    __shared__ __align__(16) float q_s[WA_ * HD_];   // 6272 B
    __shared__ __align__(16) float v_s[KV_ * HD_];   // 16384 B
    __shared__ __align__(16) float p_s[WA_ * 132];   // 25872 B (stride mult of 4)
    __shared__ float inv_s[WA_];

    // ---- load Q ----
    const int wy = w >> 3, wx = w & 7;
    for (int idx = tid; idx < WA_ * HD_; idx += 256) {
        int i = idx >> 5, d = idx & 31;
        int iy = i / WS_, ix = i % WS_;
        int pos = (wy * WS_ + iy) * RES_ + wx * WS_ + ix;
        q_s[idx] = qkv0[((size_t)b * P_ + pos) * 384 + h * HD_ + d];
    }

    // ---- gather K (regs, as f32x2 pairs) and V (smem) ----
    const int j = tid & 127;
    const float* basep;
    if (j < TOPK_) {
        int pos = idx0[w * TOPK_ + j];
        basep = qkv0 + ((size_t)b * P_ + pos) * 384;
    } else {
        int pos = idx1[w * TOPK_ + (j - TOPK_)];
        basep = qkv1 + ((size_t)b * NQ_ + pos) * 384;
    }
    const ulonglong2* kpv = (const ulonglong2*)(basep + C_ + h * HD_);
    ulonglong2 kp2[8];
#pragma unroll
    for (int t = 0; t < 8; t++) kp2[t] = kpv[t];

    if (tid < 128) {
        const float* vp = basep + 2 * C_ + h * HD_;
#pragma unroll
        for (int d4 = 0; d4 < 8; d4++)
            *(float4*)&v_s[j * HD_ + d4 * 4] = *(const float4*)(vp + d4 * 4);
    }
    __syncthreads();

    // ---- QK^T * scale + rpb ----
    const float scale = 0.17677669529663687f;
    const float* rpb_wh = rpb + ((size_t)(w * H_ + h) * WA_) * KV_;
    const int iBeg = (tid < 128) ? 0 : 25;
    const int iEnd = (tid < 128) ? 25 : WA_;
    for (int i = iBeg; i < iEnd; i++) {
        unsigned long long acc = 0ull;
        const ulonglong2* qrow = (const ulonglong2*)&q_s[i * HD_];
#pragma unroll
        for (int t = 0; t < 8; t++) {
            ulonglong2 qv = qrow[t];
            fma2(acc, qv.x, kp2[t].x);
            fma2(acc, qv.y, kp2[t].y);
        }
        float2 af;
        memcpy(&af, &acc, 8);
        p_s[i * 132 + j] = fmaf(af.x + af.y, scale, rpb_wh[i * KV_ + j]);
    }
    __syncthreads();

    // ---- softmax: one warp per row ----
    const int lane = tid & 31, wrp = tid >> 5;
    for (int i = wrp; i < WA_; i += 8) {
        float x0 = p_s[i * 132 + lane];
        float x1 = p_s[i * 132 + lane + 32];
        float x2 = p_s[i * 132 + lane + 64];
        float x3 = p_s[i * 132 + lane + 96];
        float m = fmaxf(fmaxf(x0, x1), fmaxf(x2, x3));
#pragma unroll
        for (int off = 16; off; off >>= 1) m = fmaxf(m, __shfl_xor_sync(0xffffffffu, m, off));
        float e0 = __expf(x0 - m), e1 = __expf(x1 - m);
        float e2 = __expf(x2 - m), e3 = __expf(x3 - m);
        float s = e0 + e1 + e2 + e3;
#pragma unroll
        for (int off = 16; off; off >>= 1) s += __shfl_xor_sync(0xffffffffu, s, off);
        p_s[i * 132 + lane] = e0;
        p_s[i * 132 + lane + 32] = e1;
        p_s[i * 132 + lane + 64] = e2;
        p_s[i * 132 + lane + 96] = e3;
        if (lane == 0) inv_s[i] = 1.f / s;
    }
    __syncthreads();

    // ---- PV: 196 threads, each (i, 8 d's), packed f32x2 ----
    if (tid < WA_ * 4) {
        const int i = tid >> 2;
        const int d0 = (tid & 3) * 8;
        const int vi = d0 >> 2;                  // ulonglong2 offset within v row
        unsigned long long a0 = 0, a1 = 0, a2 = 0, a3 = 0;
        const float* prow = &p_s[i * 132];
        const ulonglong2* vrow = (const ulonglong2*)v_s;   // 8 ull2 per key row
#pragma unroll 4
        for (int jj = 0; jj < KV_; jj += 4) {
            float4 p4 = *(const float4*)&prow[jj];
#pragma unroll
            for (int u = 0; u < 4; u++) {
                float pv = (u == 0) ? p4.x : (u == 1) ? p4.y : (u == 2) ? p4.z : p4.w;
                unsigned long long pd = dup2(pv);
                ulonglong2 va = vrow[(jj + u) * 8 + vi];
                ulonglong2 vb = vrow[(jj + u) * 8 + vi + 1];
                fma2(a0, pd, va.x);
                fma2(a1, pd, va.y);
                fma2(a2, pd, vb.x);
                fma2(a3, pd, vb.y);
            }
        }
        const float inv = inv_s[i];
        float2 f0, f1, f2, f3;
        memcpy(&f0, &a0, 8); memcpy(&f1, &a1, 8);
        memcpy(&f2, &a2, 8); memcpy(&f3, &a3, 8);
        size_t ob = (((size_t)(b * NQ_ + w) * WA_) + i) * C_ + h * HD_ + d0;
        float4 r0 = {f0.x * inv, f0.y * inv, f1.x * inv, f1.y * inv};
        float4 r1 = {f2.x * inv, f2.y * inv, f3.x * inv, f3.y * inv};
        *(float4*)&attn_out[ob]     = r0;
        *(float4*)&attn_out[ob + 4] = r1;
    }
}

// ============================================================
// launch
// ============================================================
extern "C" void kernel_launch(void* const* d_in, const int* in_sizes, int n_in,
                              void* d_out, int out_size)
{
    const float* x0      = (const float*)d_in[0];
    const float* x1      = (const float*)d_in[1];
    const float* qkv_w   = (const float*)d_in[2];
    const float* qkv_b   = (const float*)d_in[3];
    const float* proj_w  = (const float*)d_in[4];
    const float* proj_b  = (const float*)d_in[5];
    const float* rpb0_w1 = (const float*)d_in[6];
    const float* rpb0_b1 = (const float*)d_in[7];
    const float* rpb0_w2 = (const float*)d_in[8];
    const float* rpb0_b2 = (const float*)d_in[9];
    const float* rpb1_w1 = (const float*)d_in[10];
    const float* rpb1_b1 = (const float*)d_in[11];
    const float* rpb1_w2 = (const float*)d_in[12];
    const float* rpb1_b2 = (const float*)d_in[13];
    const float* coords0 = (const float*)d_in[14];
    const float* coords1 = (const float*)d_in[15];
    const int*   idx0    = (const int*)d_in[16];
    const int*   idx1    = (const int*)d_in[17];
    float* out = (float*)d_out;

    float *qkv0, *qkv1, *rpb, *attn_out;
    cudaGetSymbolAddress((void**)&qkv0, g_qkv0);
    cudaGetSymbolAddress((void**)&qkv1, g_qkv1);
    cudaGetSymbolAddress((void**)&rpb, g_rpb);
    cudaGetSymbolAddress((void**)&attn_out, g_attn_out);

    // 1) QKV for x0: (100352 x 128) @ (384 x 128)^T  [tf32 MMA]
    gemm_tf32<<<dim3(M0_ / 128, 384 / 128), 256>>>(x0, qkv_w, qkv_b, qkv0, M0_, 384, 128);
    // 2) QKV for x1
    gemm_tf32<<<dim3(M1_ / 128, 384 / 128), 256>>>(x1, qkv_w, qkv_b, qkv1, M1_, 384, 128);
    // 3) RPB table
    rpb_kernel<<<(NQ_ * WA_ * KV_ + 255) / 256, 256>>>(
        coords0, coords1,
        rpb0_w1, rpb0_b1, rpb0_w2, rpb0_b2,
        rpb1_w1, rpb1_b1, rpb1_w2, rpb1_b2, rpb);
    // 4) fused attention
    attn_kernel<<<dim3(NQ_, H_, B_), 256>>>(idx0, idx1, rpb, qkv0, qkv1, attn_out);
    // 5) projection [tf32 MMA]
    gemm_tf32<<<dim3(M0_ / 128, C_ / 128), 256>>>(attn_out, proj_w, proj_b, out, M0_, C_, 128);
}

// round 3
// speedup vs baseline: 1.6234x; 1.1764x over previous
#include <cuda_runtime.h>
#include <cuda_bf16.h>
#include <cstdint>
#include <cstring>

#define B_   32
#define RES_ 56
#define C_   128
#define H_   4
#define HD_  32
#define WS_  7
#define NW_  8
#define NQ_  64
#define WA_  49
#define TOPK_ 64
#define KV_  128
#define P_   3136
#define M0_  (B_*P_)
#define M1_  (B_*NQ_)

__device__ float g_qkv0[(size_t)M0_ * 384];
__device__ float g_qkv1[(size_t)M1_ * 384];
__device__ float g_rpb[(size_t)NQ_ * H_ * WA_ * KV_];
__device__ float g_attn_out[(size_t)M0_ * C_];

__device__ __forceinline__ uint32_t f2tf32(float f) {
    uint32_t r;
    asm("cvt.rna.tf32.f32 %0, %1;" : "=r"(r) : "f"(f));
    return r;
}

#define MMA_TF32(C0,C1,C2,C3,A0,A1,A2,A3,B0,B1) \
    asm volatile("mma.sync.aligned.m16n8k8.row.col.f32.tf32.tf32.f32 " \
        "{%0,%1,%2,%3},{%4,%5,%6,%7},{%8,%9},{%0,%1,%2,%3};" \
        : "+f"(C0), "+f"(C1), "+f"(C2), "+f"(C3) \
        : "r"(A0), "r"(A1), "r"(A2), "r"(A3), "r"(B0), "r"(B1))

// ============================================================
// TF32 tensor-core GEMM: C[M,N] = A[M,K] * B[N,K]^T + bias[N]
// ============================================================
__global__ __launch_bounds__(256) void gemm_tf32(
    const float* __restrict__ A, const float* __restrict__ Bm,
    const float* __restrict__ bias, float* __restrict__ C,
    int M, int N, int K)
{
    __shared__ uint32_t As[128][20];
    __shared__ uint32_t Bs[128][20];

    const int tid = threadIdx.x;
    const int m0 = blockIdx.x * 128;
    const int n0 = blockIdx.y * 128;
    const int warp = tid >> 5, lane = tid & 31;
    const int wm = (warp >> 2) * 64;
    const int wn = (warp & 3) * 32;
    const int r = lane >> 2;
    const int cI = lane & 3;

    float c[4][4][4];
#pragma unroll
    for (int mt = 0; mt < 4; mt++)
#pragma unroll
        for (int nt = 0; nt < 4; nt++)
#pragma unroll
            for (int f = 0; f < 4; f++) c[mt][nt][f] = 0.f;

    const int lr = tid >> 1;
    const int ls = (tid & 1) * 8;
    const float* Arow = A + (size_t)(m0 + lr) * K + ls;
    const float* Brow = Bm + (size_t)(n0 + lr) * K + ls;

    for (int k0 = 0; k0 < K; k0 += 16) {
        float4 a1 = *(const float4*)(Arow + k0);
        float4 a2 = *(const float4*)(Arow + k0 + 4);
        float4 b1 = *(const float4*)(Brow + k0);
        float4 b2 = *(const float4*)(Brow + k0 + 4);
        uint4 ua1 = {f2tf32(a1.x), f2tf32(a1.y), f2tf32(a1.z), f2tf32(a1.w)};
        uint4 ua2 = {f2tf32(a2.x), f2tf32(a2.y), f2tf32(a2.z), f2tf32(a2.w)};
        uint4 ub1 = {f2tf32(b1.x), f2tf32(b1.y), f2tf32(b1.z), f2tf32(b1.w)};
        uint4 ub2 = {f2tf32(b2.x), f2tf32(b2.y), f2tf32(b2.z), f2tf32(b2.w)};
        *(uint4*)&As[lr][ls]     = ua1;
        *(uint4*)&As[lr][ls + 4] = ua2;
        *(uint4*)&Bs[lr][ls]     = ub1;
        *(uint4*)&Bs[lr][ls + 4] = ub2;
        __syncthreads();

#pragma unroll
        for (int k8 = 0; k8 < 16; k8 += 8) {
            uint32_t a[4][4], b[4][2];
#pragma unroll
            for (int mt = 0; mt < 4; mt++) {
                const int mrow = wm + mt * 16 + r;
                a[mt][0] = As[mrow][k8 + cI];
                a[mt][1] = As[mrow + 8][k8 + cI];
                a[mt][2] = As[mrow][k8 + cI + 4];
                a[mt][3] = As[mrow + 8][k8 + cI + 4];
            }
#pragma unroll
            for (int nt = 0; nt < 4; nt++) {
                const int nrow = wn + nt * 8 + r;
                b[nt][0] = Bs[nrow][k8 + cI];
                b[nt][1] = Bs[nrow][k8 + cI + 4];
            }
#pragma unroll
            for (int mt = 0; mt < 4; mt++)
#pragma unroll
                for (int nt = 0; nt < 4; nt++)
                    MMA_TF32(c[mt][nt][0], c[mt][nt][1], c[mt][nt][2], c[mt][nt][3],
                             a[mt][0], a[mt][1], a[mt][2], a[mt][3],
                             b[nt][0], b[nt][1]);
        }
        __syncthreads();
    }

#pragma unroll
    for (int mt = 0; mt < 4; mt++) {
        const int row = m0 + wm + mt * 16 + r;
#pragma unroll
        for (int nt = 0; nt < 4; nt++) {
            const int col = n0 + wn + nt * 8 + cI * 2;
            float2 bb = *(const float2*)&bias[col];
            float2 o0 = {c[mt][nt][0] + bb.x, c[mt][nt][1] + bb.y};
            float2 o1 = {c[mt][nt][2] + bb.x, c[mt][nt][3] + bb.y};
            *(float2*)&C[(size_t)row * N + col]       = o0;
            *(float2*)&C[(size_t)(row + 8) * N + col] = o1;
        }
    }
}

// ============================================================
// RPB MLP precompute
// ============================================================
__global__ void rpb_kernel(
    const float* __restrict__ coords0, const float* __restrict__ coords1,
    const float* __restrict__ w1a, const float* __restrict__ b1a,
    const float* __restrict__ w2a, const float* __restrict__ b2a,
    const float* __restrict__ w1b, const float* __restrict__ b1b,
    const float* __restrict__ w2b, const float* __restrict__ b2b,
    float* __restrict__ rpb)
{
    int t = blockIdx.x * blockDim.x + threadIdx.x;
    const int TOT = NQ_ * WA_ * KV_;
    if (t >= TOT) return;
    int j = t & 127;
    int i = (t >> 7) % WA_;
    int w = t / (KV_ * WA_);

    const float *co, *w1, *b1, *w2, *b2;
    int jj;
    if (j < TOPK_) { co = coords0; jj = j;          w1 = w1a; b1 = b1a; w2 = w2a; b2 = b2a; }
    else           { co = coords1; jj = j - TOPK_;  w1 = w1b; b1 = b1b; w2 = w2b; b2 = b2b; }

    size_t cbase = ((size_t)(w * WA_ + i) * TOPK_ + jj) * 2;
    float cy = co[cbase + 0];
    float cx = co[cbase + 1];

    float o0 = b2[0], o1 = b2[1], o2 = b2[2], o3 = b2[3];
#pragma unroll
    for (int tt = 0; tt < HD_; tt++) {
        float hsum = fmaxf(fmaf(w1[tt * 2], cy, fmaf(w1[tt * 2 + 1], cx, b1[tt])), 0.f);
        o0 = fmaf(w2[0 * HD_ + tt], hsum, o0);
        o1 = fmaf(w2[1 * HD_ + tt], hsum, o1);
        o2 = fmaf(w2[2 * HD_ + tt], hsum, o2);
        o3 = fmaf(w2[3 * HD_ + tt], hsum, o3);
    }
    size_t base = ((size_t)(w * H_) * WA_ + i) * KV_ + j;
    const size_t hstride = (size_t)WA_ * KV_;
    rpb[base + 0 * hstride] = o0;
    rpb[base + 1 * hstride] = o1;
    rpb[base + 2 * hstride] = o2;
    rpb[base + 3 * hstride] = o3;
}

// ============================================================
// Tensor-core attention: one block per (w, b, h)
//   QK (64x128x32 tf32 mma) + rpb + softmax + PV (64x32x128 tf32 mma)
// dyn smem layout:
//   k_s  u32 [128][36]  @ 0       (18432 B)
//   q_s  u32 [64][36]   @ 18432   ( 9216 B)
//   vT_s u32 [32][132]  @ 27648   (16896 B)
//   p_s  f32 [64][132]  @ 44544   (33792 B)
//   inv  f32 [64]       @ 78336   (  256 B)   total 78592
// ============================================================
#define SMEM_ATTN 78592

__global__ __launch_bounds__(256) void attn_mma(
    const int* __restrict__ idx0, const int* __restrict__ idx1,
    const float* __restrict__ rpb,
    const float* __restrict__ qkv0, const float* __restrict__ qkv1,
    float* __restrict__ attn_out)
{
    extern __shared__ char smem_raw[];
    uint32_t* k_s  = (uint32_t*)(smem_raw);
    uint32_t* q_s  = (uint32_t*)(smem_raw + 18432);
    uint32_t* vT_s = (uint32_t*)(smem_raw + 27648);
    float*    p_s  = (float*)   (smem_raw + 44544);
    float*    inv_s= (float*)   (smem_raw + 78336);

    const int w = blockIdx.x, b = blockIdx.y, h = blockIdx.z;
    const int tid = threadIdx.x;
    const int warp = tid >> 5, lane = tid & 31;
    const int r = lane >> 2, cI = lane & 3;

    // ---- gather K (threads 0-127) / V transposed (threads 128-255) ----
    const int j = tid & 127;
    const float* basep;
    if (j < TOPK_) basep = qkv0 + ((size_t)b * P_ + idx0[w * TOPK_ + j]) * 384;
    else           basep = qkv1 + ((size_t)b * NQ_ + idx1[w * TOPK_ + (j - TOPK_)]) * 384;

    if (tid < 128) {
        const float4* kp = (const float4*)(basep + C_ + h * HD_);
#pragma unroll
        for (int t4 = 0; t4 < 8; t4++) {
            float4 kk = kp[t4];
            uint4 u = {f2tf32(kk.x), f2tf32(kk.y), f2tf32(kk.z), f2tf32(kk.w)};
            *(uint4*)&k_s[j * 36 + t4 * 4] = u;
        }
    } else {
        const float4* vp = (const float4*)(basep + 2 * C_ + h * HD_);
#pragma unroll
        for (int t4 = 0; t4 < 8; t4++) {
            float4 vv = vp[t4];
            vT_s[(t4 * 4 + 0) * 132 + j] = f2tf32(vv.x);
            vT_s[(t4 * 4 + 1) * 132 + j] = f2tf32(vv.y);
            vT_s[(t4 * 4 + 2) * 132 + j] = f2tf32(vv.z);
            vT_s[(t4 * 4 + 3) * 132 + j] = f2tf32(vv.w);
        }
    }

    // ---- load Q (49 rows, pad to 64 with zeros) ----
    const int wy = w >> 3, wx = w & 7;
    for (int idx = tid; idx < 64 * HD_; idx += 256) {
        int i = idx >> 5, d = idx & 31;
        uint32_t val = 0u;
        if (i < WA_) {
            int pos = (wy * WS_ + i / WS_) * RES_ + wx * WS_ + i % WS_;
            val = f2tf32(qkv0[((size_t)b * P_ + pos) * 384 + h * HD_ + d]);
        }
        q_s[i * 36 + d] = val;
    }
    __syncthreads();

    // ---- QK: M=64 N=128 K=32; warp tile 32x32 (mt=2, nt=4) ----
    {
        const int wm = (warp & 1) * 32, wn = (warp >> 1) * 32;
        float c[2][4][4];
#pragma unroll
        for (int mt = 0; mt < 2; mt++)
#pragma unroll
            for (int nt = 0; nt < 4; nt++)
#pragma unroll
                for (int f = 0; f < 4; f++) c[mt][nt][f] = 0.f;

#pragma unroll
        for (int k8 = 0; k8 < 32; k8 += 8) {
            uint32_t a[2][4], bb[4][2];
#pragma unroll
            for (int mt = 0; mt < 2; mt++) {
                const int mrow = wm + mt * 16 + r;
                a[mt][0] = q_s[mrow * 36 + k8 + cI];
                a[mt][1] = q_s[(mrow + 8) * 36 + k8 + cI];
                a[mt][2] = q_s[mrow * 36 + k8 + cI + 4];
                a[mt][3] = q_s[(mrow + 8) * 36 + k8 + cI + 4];
            }
#pragma unroll
            for (int nt = 0; nt < 4; nt++) {
                const int nrow = wn + nt * 8 + r;
                bb[nt][0] = k_s[nrow * 36 + k8 + cI];
                bb[nt][1] = k_s[nrow * 36 + k8 + cI + 4];
            }
#pragma unroll
            for (int mt = 0; mt < 2; mt++)
#pragma unroll
                for (int nt = 0; nt < 4; nt++)
                    MMA_TF32(c[mt][nt][0], c[mt][nt][1], c[mt][nt][2], c[mt][nt][3],
                             a[mt][0], a[mt][1], a[mt][2], a[mt][3],
                             bb[nt][0], bb[nt][1]);
        }

        // epilogue: scale + rpb, rows>=49 forced to 0
        const float scale = 0.17677669529663687f;
        const float* rpb_wh = rpb + (size_t)(w * H_ + h) * WA_ * KV_;
#pragma unroll
        for (int mt = 0; mt < 2; mt++) {
            const int row0 = wm + mt * 16 + r;
            const int row1 = row0 + 8;
#pragma unroll
            for (int nt = 0; nt < 4; nt++) {
                const int col = wn + nt * 8 + cI * 2;
                if (row0 < WA_) {
                    p_s[row0 * 132 + col]     = fmaf(c[mt][nt][0], scale, rpb_wh[row0 * KV_ + col]);
                    p_s[row0 * 132 + col + 1] = fmaf(c[mt][nt][1], scale, rpb_wh[row0 * KV_ + col + 1]);
                } else {
                    p_s[row0 * 132 + col] = 0.f; p_s[row0 * 132 + col + 1] = 0.f;
                }
                if (row1 < WA_) {
                    p_s[row1 * 132 + col]     = fmaf(c[mt][nt][2], scale, rpb_wh[row1 * KV_ + col]);
                    p_s[row1 * 132 + col + 1] = fmaf(c[mt][nt][3], scale, rpb_wh[row1 * KV_ + col + 1]);
                } else {
                    p_s[row1 * 132 + col] = 0.f; p_s[row1 * 132 + col + 1] = 0.f;
                }
            }
        }
    }
    __syncthreads();

    // ---- softmax: one warp per row, keep unnormalized exp; inv at end ----
    for (int i = warp; i < WA_; i += 8) {
        float x0 = p_s[i * 132 + lane];
        float x1 = p_s[i * 132 + lane + 32];
        float x2 = p_s[i * 132 + lane + 64];
        float x3 = p_s[i * 132 + lane + 96];
        float m = fmaxf(fmaxf(x0, x1), fmaxf(x2, x3));
#pragma unroll
        for (int off = 16; off; off >>= 1) m = fmaxf(m, __shfl_xor_sync(0xffffffffu, m, off));
        float e0 = __expf(x0 - m), e1 = __expf(x1 - m);
        float e2 = __expf(x2 - m), e3 = __expf(x3 - m);
        float s = e0 + e1 + e2 + e3;
#pragma unroll
        for (int off = 16; off; off >>= 1) s += __shfl_xor_sync(0xffffffffu, s, off);
        p_s[i * 132 + lane]      = e0;
        p_s[i * 132 + lane + 32] = e1;
        p_s[i * 132 + lane + 64] = e2;
        p_s[i * 132 + lane + 96] = e3;
        if (lane == 0) inv_s[i] = 1.f / s;
    }
    __syncthreads();

    // ---- PV: M=64 N=32 K=128; warp tile 16x16 (4 warps M, 2 warps N) ----
    {
        const int wm = (warp >> 1) * 16, wn = (warp & 1) * 16;
        float c[2][4];
#pragma unroll
        for (int nt = 0; nt < 2; nt++)
#pragma unroll
            for (int f = 0; f < 4; f++) c[nt][f] = 0.f;

        const int mrow = wm + r;
#pragma unroll
        for (int k8 = 0; k8 < KV_; k8 += 8) {
            uint32_t a0 = f2tf32(p_s[mrow * 132 + k8 + cI]);
            uint32_t a1 = f2tf32(p_s[(mrow + 8) * 132 + k8 + cI]);
            uint32_t a2 = f2tf32(p_s[mrow * 132 + k8 + cI + 4]);
            uint32_t a3 = f2tf32(p_s[(mrow + 8) * 132 + k8 + cI + 4]);
#pragma unroll
            for (int nt = 0; nt < 2; nt++) {
                const int nrow = wn + nt * 8 + r;
                uint32_t b0 = vT_s[nrow * 132 + k8 + cI];
                uint32_t b1 = vT_s[nrow * 132 + k8 + cI + 4];
                MMA_TF32(c[nt][0], c[nt][1], c[nt][2], c[nt][3],
                         a0, a1, a2, a3, b0, b1);
            }
        }

        // epilogue: normalize and store
        const int row0 = wm + r, row1 = wm + r + 8;
#pragma unroll
        for (int nt = 0; nt < 2; nt++) {
            const int col = wn + nt * 8 + cI * 2;
            if (row0 < WA_) {
                float inv = inv_s[row0];
                float2 o = {c[nt][0] * inv, c[nt][1] * inv};
                *(float2*)&attn_out[(((size_t)(b * NQ_ + w) * WA_) + row0) * C_ + h * HD_ + col] = o;
            }
            if (row1 < WA_) {
                float inv = inv_s[row1];
                float2 o = {c[nt][2] * inv, c[nt][3] * inv};
                *(float2*)&attn_out[(((size_t)(b * NQ_ + w) * WA_) + row1) * C_ + h * HD_ + col] = o;
            }
        }
    }
}

// ============================================================
// launch
// ============================================================
extern "C" void kernel_launch(void* const* d_in, const int* in_sizes, int n_in,
                              void* d_out, int out_size)
{
    const float* x0      = (const float*)d_in[0];
    const float* x1      = (const float*)d_in[1];
    const float* qkv_w   = (const float*)d_in[2];
    const float* qkv_b   = (const float*)d_in[3];
    const float* proj_w  = (const float*)d_in[4];
    const float* proj_b  = (const float*)d_in[5];
    const float* rpb0_w1 = (const float*)d_in[6];
    const float* rpb0_b1 = (const float*)d_in[7];
    const float* rpb0_w2 = (const float*)d_in[8];
    const float* rpb0_b2 = (const float*)d_in[9];
    const float* rpb1_w1 = (const float*)d_in[10];
    const float* rpb1_b1 = (const float*)d_in[11];
    const float* rpb1_w2 = (const float*)d_in[12];
    const float* rpb1_b2 = (const float*)d_in[13];
    const float* coords0 = (const float*)d_in[14];
    const float* coords1 = (const float*)d_in[15];
    const int*   idx0    = (const int*)d_in[16];
    const int*   idx1    = (const int*)d_in[17];
    float* out = (float*)d_out;

    float *qkv0, *qkv1, *rpb, *attn_out;
    cudaGetSymbolAddress((void**)&qkv0, g_qkv0);
    cudaGetSymbolAddress((void**)&qkv1, g_qkv1);
    cudaGetSymbolAddress((void**)&rpb, g_rpb);
    cudaGetSymbolAddress((void**)&attn_out, g_attn_out);

    cudaFuncSetAttribute(attn_mma, cudaFuncAttributeMaxDynamicSharedMemorySize, SMEM_ATTN);

    gemm_tf32<<<dim3(M0_ / 128, 384 / 128), 256>>>(x0, qkv_w, qkv_b, qkv0, M0_, 384, 128);
    gemm_tf32<<<dim3(M1_ / 128, 384 / 128), 256>>>(x1, qkv_w, qkv_b, qkv1, M1_, 384, 128);
    rpb_kernel<<<(NQ_ * WA_ * KV_ + 255) / 256, 256>>>(
        coords0, coords1,
        rpb0_w1, rpb0_b1, rpb0_w2, rpb0_b2,
        rpb1_w1, rpb1_b1, rpb1_w2, rpb1_b2, rpb);
    attn_mma<<<dim3(NQ_, B_, H_), 256, SMEM_ATTN>>>(idx0, idx1, rpb, qkv0, qkv1, attn_out);
    gemm_tf32<<<dim3(M0_ / 128, C_ / 128), 256>>>(attn_out, proj_w, proj_b, out, M0_, C_, 128);
}

// round 4
// speedup vs baseline: 1.9364x; 1.1928x over previous
#include <cuda_runtime.h>
#include <cuda_bf16.h>
#include <cstdint>
#include <cstring>

#define B_   32
#define RES_ 56
#define C_   128
#define H_   4
#define HD_  32
#define WS_  7
#define NW_  8
#define NQ_  64
#define WA_  49
#define TOPK_ 64
#define KV_  128
#define P_   3136
#define M0_  (B_*P_)
#define M1_  (B_*NQ_)

__device__ float g_qkv0[(size_t)M0_ * 384];
__device__ float g_qkv1[(size_t)M1_ * 384];
__device__ float g_rpb[(size_t)NQ_ * H_ * WA_ * KV_];
__device__ float g_attn_out[(size_t)M0_ * C_];

__device__ __forceinline__ uint32_t f2tf32(float f) {
    uint32_t r;
    asm("cvt.rna.tf32.f32 %0, %1;" : "=r"(r) : "f"(f));
    return r;
}

#define MMA_TF32(C0,C1,C2,C3,A0,A1,A2,A3,B0,B1) \
    asm volatile("mma.sync.aligned.m16n8k8.row.col.f32.tf32.tf32.f32 " \
        "{%0,%1,%2,%3},{%4,%5,%6,%7},{%8,%9},{%0,%1,%2,%3};" \
        : "+f"(C0), "+f"(C1), "+f"(C2), "+f"(C3) \
        : "r"(A0), "r"(A1), "r"(A2), "r"(A3), "r"(B0), "r"(B1))

// ============================================================
// TF32 GEMM: C[M,N] = A[M,K] * B[N,K]^T + bias[N]; BK=32
// ============================================================
__global__ __launch_bounds__(256) void gemm_tf32(
    const float* __restrict__ A, const float* __restrict__ Bm,
    const float* __restrict__ bias, float* __restrict__ C,
    int M, int N, int K)
{
    __shared__ uint32_t As[128][36];
    __shared__ uint32_t Bs[128][36];

    const int tid = threadIdx.x;
    const int m0 = blockIdx.x * 128;
    const int n0 = blockIdx.y * 128;
    const int warp = tid >> 5, lane = tid & 31;
    const int wm = (warp >> 2) * 64;
    const int wn = (warp & 3) * 32;
    const int r = lane >> 2;
    const int cI = lane & 3;

    float c[4][4][4];
#pragma unroll
    for (int mt = 0; mt < 4; mt++)
#pragma unroll
        for (int nt = 0; nt < 4; nt++)
#pragma unroll
            for (int f = 0; f < 4; f++) c[mt][nt][f] = 0.f;

    const int lr = tid >> 1;
    const int ls = (tid & 1) * 16;
    const float* Arow = A + (size_t)(m0 + lr) * K + ls;
    const float* Brow = Bm + (size_t)(n0 + lr) * K + ls;

    for (int k0 = 0; k0 < K; k0 += 32) {
#pragma unroll
        for (int q4 = 0; q4 < 4; q4++) {
            float4 a4 = *(const float4*)(Arow + k0 + q4 * 4);
            float4 b4 = *(const float4*)(Brow + k0 + q4 * 4);
            uint4 ua = {f2tf32(a4.x), f2tf32(a4.y), f2tf32(a4.z), f2tf32(a4.w)};
            uint4 ub = {f2tf32(b4.x), f2tf32(b4.y), f2tf32(b4.z), f2tf32(b4.w)};
            *(uint4*)&As[lr][ls + q4 * 4] = ua;
            *(uint4*)&Bs[lr][ls + q4 * 4] = ub;
        }
        __syncthreads();

#pragma unroll
        for (int k8 = 0; k8 < 32; k8 += 8) {
            uint32_t a[4][4], b[4][2];
#pragma unroll
            for (int mt = 0; mt < 4; mt++) {
                const int mrow = wm + mt * 16 + r;
                a[mt][0] = As[mrow][k8 + cI];
                a[mt][1] = As[mrow + 8][k8 + cI];
                a[mt][2] = As[mrow][k8 + cI + 4];
                a[mt][3] = As[mrow + 8][k8 + cI + 4];
            }
#pragma unroll
            for (int nt = 0; nt < 4; nt++) {
                const int nrow = wn + nt * 8 + r;
                b[nt][0] = Bs[nrow][k8 + cI];
                b[nt][1] = Bs[nrow][k8 + cI + 4];
            }
#pragma unroll
            for (int mt = 0; mt < 4; mt++)
#pragma unroll
                for (int nt = 0; nt < 4; nt++)
                    MMA_TF32(c[mt][nt][0], c[mt][nt][1], c[mt][nt][2], c[mt][nt][3],
                             a[mt][0], a[mt][1], a[mt][2], a[mt][3],
                             b[nt][0], b[nt][1]);
        }
        __syncthreads();
    }

#pragma unroll
    for (int mt = 0; mt < 4; mt++) {
        const int row = m0 + wm + mt * 16 + r;
#pragma unroll
        for (int nt = 0; nt < 4; nt++) {
            const int col = n0 + wn + nt * 8 + cI * 2;
            float2 bb = *(const float2*)&bias[col];
            float2 o0 = {c[mt][nt][0] + bb.x, c[mt][nt][1] + bb.y};
            float2 o1 = {c[mt][nt][2] + bb.x, c[mt][nt][3] + bb.y};
            *(float2*)&C[(size_t)row * N + col]       = o0;
            *(float2*)&C[(size_t)(row + 8) * N + col] = o1;
        }
    }
}

// ============================================================
// RPB MLP precompute
// ============================================================
__global__ void rpb_kernel(
    const float* __restrict__ coords0, const float* __restrict__ coords1,
    const float* __restrict__ w1a, const float* __restrict__ b1a,
    const float* __restrict__ w2a, const float* __restrict__ b2a,
    const float* __restrict__ w1b, const float* __restrict__ b1b,
    const float* __restrict__ w2b, const float* __restrict__ b2b,
    float* __restrict__ rpb)
{
    int t = blockIdx.x * blockDim.x + threadIdx.x;
    const int TOT = NQ_ * WA_ * KV_;
    if (t >= TOT) return;
    int j = t & 127;
    int i = (t >> 7) % WA_;
    int w = t / (KV_ * WA_);

    const float *co, *w1, *b1, *w2, *b2;
    int jj;
    if (j < TOPK_) { co = coords0; jj = j;          w1 = w1a; b1 = b1a; w2 = w2a; b2 = b2a; }
    else           { co = coords1; jj = j - TOPK_;  w1 = w1b; b1 = b1b; w2 = w2b; b2 = b2b; }

    size_t cbase = ((size_t)(w * WA_ + i) * TOPK_ + jj) * 2;
    float cy = co[cbase + 0];
    float cx = co[cbase + 1];

    float o0 = b2[0], o1 = b2[1], o2 = b2[2], o3 = b2[3];
#pragma unroll
    for (int tt = 0; tt < HD_; tt++) {
        float hsum = fmaxf(fmaf(w1[tt * 2], cy, fmaf(w1[tt * 2 + 1], cx, b1[tt])), 0.f);
        o0 = fmaf(w2[0 * HD_ + tt], hsum, o0);
        o1 = fmaf(w2[1 * HD_ + tt], hsum, o1);
        o2 = fmaf(w2[2 * HD_ + tt], hsum, o2);
        o3 = fmaf(w2[3 * HD_ + tt], hsum, o3);
    }
    size_t base = ((size_t)(w * H_) * WA_ + i) * KV_ + j;
    const size_t hstride = (size_t)WA_ * KV_;
    rpb[base + 0 * hstride] = o0;
    rpb[base + 1 * hstride] = o1;
    rpb[base + 2 * hstride] = o2;
    rpb[base + 3 * hstride] = o3;
}

// ============================================================
// Tensor-core attention: one block per (w, b, h)
// smem (69376 B total) -> 3 CTAs/SM:
//   k_s  u32 [128][36]  @ 0       (18432)
//   vT_s u32 [32][132]  @ 18432   (16896)
//   p_s  f32 [64][132]  @ 35328   (33792)   q_s aliases first 9216 B
//   inv  f32 [64]       @ 69120   (  256)
// ============================================================
#define SMEM_ATTN 69376

__global__ __launch_bounds__(256, 3) void attn_mma(
    const int* __restrict__ idx0, const int* __restrict__ idx1,
    const float* __restrict__ rpb,
    const float* __restrict__ qkv0, const float* __restrict__ qkv1,
    float* __restrict__ attn_out)
{
    extern __shared__ char smem_raw[];
    uint32_t* k_s  = (uint32_t*)(smem_raw);
    uint32_t* vT_s = (uint32_t*)(smem_raw + 18432);
    float*    p_s  = (float*)   (smem_raw + 35328);
    uint32_t* q_s  = (uint32_t*)(smem_raw + 35328);   // alias: dead after QK mma
    float*    inv_s= (float*)   (smem_raw + 69120);

    const int w = blockIdx.x, b = blockIdx.y, h = blockIdx.z;
    const int tid = threadIdx.x;
    const int warp = tid >> 5, lane = tid & 31;
    const int r = lane >> 2, cI = lane & 3;

    // ---- gather K (threads 0-127) / V transposed (threads 128-255) ----
    const int j = tid & 127;
    const float* basep;
    if (j < TOPK_) basep = qkv0 + ((size_t)b * P_ + idx0[w * TOPK_ + j]) * 384;
    else           basep = qkv1 + ((size_t)b * NQ_ + idx1[w * TOPK_ + (j - TOPK_)]) * 384;

    if (tid < 128) {
        const float4* kp = (const float4*)(basep + C_ + h * HD_);
#pragma unroll
        for (int t4 = 0; t4 < 8; t4++) {
            float4 kk = kp[t4];
            uint4 u = {f2tf32(kk.x), f2tf32(kk.y), f2tf32(kk.z), f2tf32(kk.w)};
            *(uint4*)&k_s[j * 36 + t4 * 4] = u;
        }
    } else {
        const float4* vp = (const float4*)(basep + 2 * C_ + h * HD_);
#pragma unroll
        for (int t4 = 0; t4 < 8; t4++) {
            float4 vv = vp[t4];
            vT_s[(t4 * 4 + 0) * 132 + j] = f2tf32(vv.x);
            vT_s[(t4 * 4 + 1) * 132 + j] = f2tf32(vv.y);
            vT_s[(t4 * 4 + 2) * 132 + j] = f2tf32(vv.z);
            vT_s[(t4 * 4 + 3) * 132 + j] = f2tf32(vv.w);
        }
    }

    // ---- load Q (49 rows, pad to 64 with zeros) into aliased q_s ----
    const int wy = w >> 3, wx = w & 7;
    for (int idx = tid; idx < 64 * HD_; idx += 256) {
        int i = idx >> 5, d = idx & 31;
        uint32_t val = 0u;
        if (i < WA_) {
            int pos = (wy * WS_ + i / WS_) * RES_ + wx * WS_ + i % WS_;
            val = f2tf32(qkv0[((size_t)b * P_ + pos) * 384 + h * HD_ + d]);
        }
        q_s[i * 36 + d] = val;
    }
    __syncthreads();

    // ---- QK: M=64 N=128 K=32; warp tile 32x32 ----
    float cq[2][4][4];
    {
        const int wm = (warp & 1) * 32, wn = (warp >> 1) * 32;
#pragma unroll
        for (int mt = 0; mt < 2; mt++)
#pragma unroll
            for (int nt = 0; nt < 4; nt++)
#pragma unroll
                for (int f = 0; f < 4; f++) cq[mt][nt][f] = 0.f;

#pragma unroll
        for (int k8 = 0; k8 < 32; k8 += 8) {
            uint32_t a[2][4], bb[4][2];
#pragma unroll
            for (int mt = 0; mt < 2; mt++) {
                const int mrow = wm + mt * 16 + r;
                a[mt][0] = q_s[mrow * 36 + k8 + cI];
                a[mt][1] = q_s[(mrow + 8) * 36 + k8 + cI];
                a[mt][2] = q_s[mrow * 36 + k8 + cI + 4];
                a[mt][3] = q_s[(mrow + 8) * 36 + k8 + cI + 4];
            }
#pragma unroll
            for (int nt = 0; nt < 4; nt++) {
                const int nrow = wn + nt * 8 + r;
                bb[nt][0] = k_s[nrow * 36 + k8 + cI];
                bb[nt][1] = k_s[nrow * 36 + k8 + cI + 4];
            }
#pragma unroll
            for (int mt = 0; mt < 2; mt++)
#pragma unroll
                for (int nt = 0; nt < 4; nt++)
                    MMA_TF32(cq[mt][nt][0], cq[mt][nt][1], cq[mt][nt][2], cq[mt][nt][3],
                             a[mt][0], a[mt][1], a[mt][2], a[mt][3],
                             bb[nt][0], bb[nt][1]);
        }
    }
    __syncthreads();   // q_s dead; safe to overwrite with p_s

    // ---- epilogue: store raw logits (no loads) ----
    {
        const int wm = (warp & 1) * 32, wn = (warp >> 1) * 32;
#pragma unroll
        for (int mt = 0; mt < 2; mt++) {
            const int row0 = wm + mt * 16 + r;
            const int row1 = row0 + 8;
#pragma unroll
            for (int nt = 0; nt < 4; nt++) {
                const int col = wn + nt * 8 + cI * 2;
                if (row0 < WA_) {
                    p_s[row0 * 132 + col]     = cq[mt][nt][0];
                    p_s[row0 * 132 + col + 1] = cq[mt][nt][1];
                }
                if (row1 < WA_) {
                    p_s[row1 * 132 + col]     = cq[mt][nt][2];
                    p_s[row1 * 132 + col + 1] = cq[mt][nt][3];
                }
            }
        }
        // zero pad rows >= WA_ so PV A-fragments stay finite
        for (int idx = tid; idx < (64 - WA_) * 132; idx += 256)
            p_s[WA_ * 132 + idx] = 0.f;
    }
    __syncthreads();

    // ---- softmax (fused scale + rpb, coalesced rpb reads) ----
    const float scale = 0.17677669529663687f;
    const float* rpb_wh = rpb + (size_t)(w * H_ + h) * WA_ * KV_;
    for (int i = warp; i < WA_; i += 8) {
        const float* rrow = rpb_wh + i * KV_;
        float x0 = fmaf(p_s[i * 132 + lane],      scale, rrow[lane]);
        float x1 = fmaf(p_s[i * 132 + lane + 32], scale, rrow[lane + 32]);
        float x2 = fmaf(p_s[i * 132 + lane + 64], scale, rrow[lane + 64]);
        float x3 = fmaf(p_s[i * 132 + lane + 96], scale, rrow[lane + 96]);
        float m = fmaxf(fmaxf(x0, x1), fmaxf(x2, x3));
#pragma unroll
        for (int off = 16; off; off >>= 1) m = fmaxf(m, __shfl_xor_sync(0xffffffffu, m, off));
        float e0 = __expf(x0 - m), e1 = __expf(x1 - m);
        float e2 = __expf(x2 - m), e3 = __expf(x3 - m);
        float s = e0 + e1 + e2 + e3;
#pragma unroll
        for (int off = 16; off; off >>= 1) s += __shfl_xor_sync(0xffffffffu, s, off);
        p_s[i * 132 + lane]      = e0;
        p_s[i * 132 + lane + 32] = e1;
        p_s[i * 132 + lane + 64] = e2;
        p_s[i * 132 + lane + 96] = e3;
        if (lane == 0) inv_s[i] = 1.f / s;
    }
    __syncthreads();

    // ---- PV: M=64 N=32 K=128; warp tile 16x16 ----
    {
        const int wm = (warp >> 1) * 16, wn = (warp & 1) * 16;
        float c[2][4];
#pragma unroll
        for (int nt = 0; nt < 2; nt++)
#pragma unroll
            for (int f = 0; f < 4; f++) c[nt][f] = 0.f;

        const int mrow = wm + r;
#pragma unroll
        for (int k8 = 0; k8 < KV_; k8 += 8) {
            uint32_t a0 = f2tf32(p_s[mrow * 132 + k8 + cI]);
            uint32_t a1 = f2tf32(p_s[(mrow + 8) * 132 + k8 + cI]);
            uint32_t a2 = f2tf32(p_s[mrow * 132 + k8 + cI + 4]);
            uint32_t a3 = f2tf32(p_s[(mrow + 8) * 132 + k8 + cI + 4]);
#pragma unroll
            for (int nt = 0; nt < 2; nt++) {
                const int nrow = wn + nt * 8 + r;
                uint32_t b0 = vT_s[nrow * 132 + k8 + cI];
                uint32_t b1 = vT_s[nrow * 132 + k8 + cI + 4];
                MMA_TF32(c[nt][0], c[nt][1], c[nt][2], c[nt][3],
                         a0, a1, a2, a3, b0, b1);
            }
        }

        const int row0 = wm + r, row1 = wm + r + 8;
#pragma unroll
        for (int nt = 0; nt < 2; nt++) {
            const int col = wn + nt * 8 + cI * 2;
            if (row0 < WA_) {
                float inv = inv_s[row0];
                float2 o = {c[nt][0] * inv, c[nt][1] * inv};
                *(float2*)&attn_out[(((size_t)(b * NQ_ + w) * WA_) + row0) * C_ + h * HD_ + col] = o;
            }
            if (row1 < WA_) {
                float inv = inv_s[row1];
                float2 o = {c[nt][2] * inv, c[nt][3] * inv};
                *(float2*)&attn_out[(((size_t)(b * NQ_ + w) * WA_) + row1) * C_ + h * HD_ + col] = o;
            }
        }
    }
}

// ============================================================
// launch
// ============================================================
extern "C" void kernel_launch(void* const* d_in, const int* in_sizes, int n_in,
                              void* d_out, int out_size)
{
    const float* x0      = (const float*)d_in[0];
    const float* x1      = (const float*)d_in[1];
    const float* qkv_w   = (const float*)d_in[2];
    const float* qkv_b   = (const float*)d_in[3];
    const float* proj_w  = (const float*)d_in[4];
    const float* proj_b  = (const float*)d_in[5];
    const float* rpb0_w1 = (const float*)d_in[6];
    const float* rpb0_b1 = (const float*)d_in[7];
    const float* rpb0_w2 = (const float*)d_in[8];
    const float* rpb0_b2 = (const float*)d_in[9];
    const float* rpb1_w1 = (const float*)d_in[10];
    const float* rpb1_b1 = (const float*)d_in[11];
    const float* rpb1_w2 = (const float*)d_in[12];
    const float* rpb1_b2 = (const float*)d_in[13];
    const float* coords0 = (const float*)d_in[14];
    const float* coords1 = (const float*)d_in[15];
    const int*   idx0    = (const int*)d_in[16];
    const int*   idx1    = (const int*)d_in[17];
    float* out = (float*)d_out;

    float *qkv0, *qkv1, *rpb, *attn_out;
    cudaGetSymbolAddress((void**)&qkv0, g_qkv0);
    cudaGetSymbolAddress((void**)&qkv1, g_qkv1);
    cudaGetSymbolAddress((void**)&rpb, g_rpb);
    cudaGetSymbolAddress((void**)&attn_out, g_attn_out);

    cudaFuncSetAttribute(attn_mma, cudaFuncAttributeMaxDynamicSharedMemorySize, SMEM_ATTN);

    gemm_tf32<<<dim3(M0_ / 128, 384 / 128), 256>>>(x0, qkv_w, qkv_b, qkv0, M0_, 384, 128);
    gemm_tf32<<<dim3(M1_ / 128, 384 / 128), 256>>>(x1, qkv_w, qkv_b, qkv1, M1_, 384, 128);
    rpb_kernel<<<(NQ_ * WA_ * KV_ + 255) / 256, 256>>>(
        coords0, coords1,
        rpb0_w1, rpb0_b1, rpb0_w2, rpb0_b2,
        rpb1_w1, rpb1_b1, rpb1_w2, rpb1_b2, rpb);
    attn_mma<<<dim3(NQ_, B_, H_), 256, SMEM_ATTN>>>(idx0, idx1, rpb, qkv0, qkv1, attn_out);
    gemm_tf32<<<dim3(M0_ / 128, C_ / 128), 256>>>(attn_out, proj_w, proj_b, out, M0_, C_, 128);
}

// round 5
// speedup vs baseline: 2.3041x; 1.1899x over previous
#include <cuda_runtime.h>
#include <cuda_bf16.h>
#include <cstdint>
#include <cstring>

#define B_   32
#define RES_ 56
#define C_   128
#define H_   4
#define HD_  32
#define WS_  7
#define NW_  8
#define NQ_  64
#define WA_  49
#define TOPK_ 64
#define KV_  128
#define P_   3136
#define M0_  (B_*P_)
#define M1_  (B_*NQ_)

__device__ float g_qkv0[(size_t)M0_ * 384];
__device__ float g_qkv1[(size_t)M1_ * 384];
__device__ float g_rpb[(size_t)NQ_ * H_ * WA_ * KV_];
__device__ float g_attn_out[(size_t)M0_ * C_];

__device__ __forceinline__ uint32_t f2tf32(float f) {
    uint32_t r;
    asm("cvt.rna.tf32.f32 %0, %1;" : "=r"(r) : "f"(f));
    return r;
}

#define MMA_TF32(C0,C1,C2,C3,A0,A1,A2,A3,B0,B1) \
    asm volatile("mma.sync.aligned.m16n8k8.row.col.f32.tf32.tf32.f32 " \
        "{%0,%1,%2,%3},{%4,%5,%6,%7},{%8,%9},{%0,%1,%2,%3};" \
        : "+f"(C0), "+f"(C1), "+f"(C2), "+f"(C3) \
        : "r"(A0), "r"(A1), "r"(A2), "r"(A3), "r"(B0), "r"(B1))

// ============================================================
// TF32 GEMM: C[M,N] = A[M,K] * B[N,K]^T + bias[N]; BK=32
// ============================================================
__global__ __launch_bounds__(256) void gemm_tf32(
    const float* __restrict__ A, const float* __restrict__ Bm,
    const float* __restrict__ bias, float* __restrict__ C,
    int M, int N, int K)
{
    __shared__ uint32_t As[128][36];
    __shared__ uint32_t Bs[128][36];

    const int tid = threadIdx.x;
    const int m0 = blockIdx.x * 128;
    const int n0 = blockIdx.y * 128;
    const int warp = tid >> 5, lane = tid & 31;
    const int wm = (warp >> 2) * 64;
    const int wn = (warp & 3) * 32;
    const int r = lane >> 2;
    const int cI = lane & 3;

    float c[4][4][4];
#pragma unroll
    for (int mt = 0; mt < 4; mt++)
#pragma unroll
        for (int nt = 0; nt < 4; nt++)
#pragma unroll
            for (int f = 0; f < 4; f++) c[mt][nt][f] = 0.f;

    const int lr = tid >> 1;
    const int ls = (tid & 1) * 16;
    const float* Arow = A + (size_t)(m0 + lr) * K + ls;
    const float* Brow = Bm + (size_t)(n0 + lr) * K + ls;

    for (int k0 = 0; k0 < K; k0 += 32) {
#pragma unroll
        for (int q4 = 0; q4 < 4; q4++) {
            float4 a4 = *(const float4*)(Arow + k0 + q4 * 4);
            float4 b4 = *(const float4*)(Brow + k0 + q4 * 4);
            uint4 ua = {f2tf32(a4.x), f2tf32(a4.y), f2tf32(a4.z), f2tf32(a4.w)};
            uint4 ub = {f2tf32(b4.x), f2tf32(b4.y), f2tf32(b4.z), f2tf32(b4.w)};
            *(uint4*)&As[lr][ls + q4 * 4] = ua;
            *(uint4*)&Bs[lr][ls + q4 * 4] = ub;
        }
        __syncthreads();

#pragma unroll
        for (int k8 = 0; k8 < 32; k8 += 8) {
            uint32_t a[4][4], b[4][2];
#pragma unroll
            for (int mt = 0; mt < 4; mt++) {
                const int mrow = wm + mt * 16 + r;
                a[mt][0] = As[mrow][k8 + cI];
                a[mt][1] = As[mrow + 8][k8 + cI];
                a[mt][2] = As[mrow][k8 + cI + 4];
                a[mt][3] = As[mrow + 8][k8 + cI + 4];
            }
#pragma unroll
            for (int nt = 0; nt < 4; nt++) {
                const int nrow = wn + nt * 8 + r;
                b[nt][0] = Bs[nrow][k8 + cI];
                b[nt][1] = Bs[nrow][k8 + cI + 4];
            }
#pragma unroll
            for (int mt = 0; mt < 4; mt++)
#pragma unroll
                for (int nt = 0; nt < 4; nt++)
                    MMA_TF32(c[mt][nt][0], c[mt][nt][1], c[mt][nt][2], c[mt][nt][3],
                             a[mt][0], a[mt][1], a[mt][2], a[mt][3],
                             b[nt][0], b[nt][1]);
        }
        __syncthreads();
    }

#pragma unroll
    for (int mt = 0; mt < 4; mt++) {
        const int row = m0 + wm + mt * 16 + r;
#pragma unroll
        for (int nt = 0; nt < 4; nt++) {
            const int col = n0 + wn + nt * 8 + cI * 2;
            float2 bb = *(const float2*)&bias[col];
            float2 o0 = {c[mt][nt][0] + bb.x, c[mt][nt][1] + bb.y};
            float2 o1 = {c[mt][nt][2] + bb.x, c[mt][nt][3] + bb.y};
            *(float2*)&C[(size_t)row * N + col]       = o0;
            *(float2*)&C[(size_t)(row + 8) * N + col] = o1;
        }
    }
}

// ============================================================
// RPB MLP precompute
// ============================================================
__global__ void rpb_kernel(
    const float* __restrict__ coords0, const float* __restrict__ coords1,
    const float* __restrict__ w1a, const float* __restrict__ b1a,
    const float* __restrict__ w2a, const float* __restrict__ b2a,
    const float* __restrict__ w1b, const float* __restrict__ b1b,
    const float* __restrict__ w2b, const float* __restrict__ b2b,
    float* __restrict__ rpb)
{
    int t = blockIdx.x * blockDim.x + threadIdx.x;
    const int TOT = NQ_ * WA_ * KV_;
    if (t >= TOT) return;
    int j = t & 127;
    int i = (t >> 7) % WA_;
    int w = t / (KV_ * WA_);

    const float *co, *w1, *b1, *w2, *b2;
    int jj;
    if (j < TOPK_) { co = coords0; jj = j;          w1 = w1a; b1 = b1a; w2 = w2a; b2 = b2a; }
    else           { co = coords1; jj = j - TOPK_;  w1 = w1b; b1 = b1b; w2 = w2b; b2 = b2b; }

    size_t cbase = ((size_t)(w * WA_ + i) * TOPK_ + jj) * 2;
    float cy = co[cbase + 0];
    float cx = co[cbase + 1];

    float o0 = b2[0], o1 = b2[1], o2 = b2[2], o3 = b2[3];
#pragma unroll
    for (int tt = 0; tt < HD_; tt++) {
        float hsum = fmaxf(fmaf(w1[tt * 2], cy, fmaf(w1[tt * 2 + 1], cx, b1[tt])), 0.f);
        o0 = fmaf(w2[0 * HD_ + tt], hsum, o0);
        o1 = fmaf(w2[1 * HD_ + tt], hsum, o1);
        o2 = fmaf(w2[2 * HD_ + tt], hsum, o2);
        o3 = fmaf(w2[3 * HD_ + tt], hsum, o3);
    }
    size_t base = ((size_t)(w * H_) * WA_ + i) * KV_ + j;
    const size_t hstride = (size_t)WA_ * KV_;
    rpb[base + 0 * hstride] = o0;
    rpb[base + 1 * hstride] = o1;
    rpb[base + 2 * hstride] = o2;
    rpb[base + 3 * hstride] = o3;
}

// ============================================================
// Tensor-core attention: one block per (w, b, h)
// smem (52480 B) -> 4 CTAs/SM target:
//   k_s  u32 [128][36] @ 0      (18432)  -- vT_s [32][132] aliases (16896)
//   p_s  f32 [64][132] @ 18432  (33792)  -- q_s [64][36] aliases head
//   inv  f32 [64]      @ 52224  (  256)
// ============================================================
#define SMEM_ATTN 52480

__global__ __launch_bounds__(256, 4) void attn_mma(
    const int* __restrict__ idx0, const int* __restrict__ idx1,
    const float* __restrict__ rpb,
    const float* __restrict__ qkv0, const float* __restrict__ qkv1,
    float* __restrict__ attn_out)
{
    extern __shared__ char smem_raw[];
    uint32_t* k_s  = (uint32_t*)(smem_raw);            // phase 1
    uint32_t* vT_s = (uint32_t*)(smem_raw);            // phase 2 alias
    float*    p_s  = (float*)   (smem_raw + 18432);
    uint32_t* q_s  = (uint32_t*)(smem_raw + 18432);    // alias (dead after QK)
    float*    inv_s= (float*)   (smem_raw + 52224);

    const int w = blockIdx.x, b = blockIdx.y, h = blockIdx.z;
    const int tid = threadIdx.x;
    const int warp = tid >> 5, lane = tid & 31;
    const int r = lane >> 2, cI = lane & 3;

    // ---- gather K: all 256 threads, 2 threads per key row ----
    const int j = tid >> 1;              // key row 0..127
    const int half = (tid & 1) * 16;     // 16-float half of the 32-float head slice
    const float* basep;
    if (j < TOPK_) basep = qkv0 + ((size_t)b * P_ + idx0[w * TOPK_ + j]) * 384;
    else           basep = qkv1 + ((size_t)b * NQ_ + idx1[w * TOPK_ + (j - TOPK_)]) * 384;

    {
        const float4* kp = (const float4*)(basep + C_ + h * HD_ + half);
#pragma unroll
        for (int t4 = 0; t4 < 4; t4++) {
            float4 kk = kp[t4];
            uint4 u = {f2tf32(kk.x), f2tf32(kk.y), f2tf32(kk.z), f2tf32(kk.w)};
            *(uint4*)&k_s[j * 36 + half + t4 * 4] = u;
        }
    }

    // ---- load Q (49 rows, pad to 64 with zeros) into aliased q_s ----
    const int wy = w >> 3, wx = w & 7;
    for (int idx = tid; idx < 64 * HD_; idx += 256) {
        int i = idx >> 5, d = idx & 31;
        uint32_t val = 0u;
        if (i < WA_) {
            int pos = (wy * WS_ + i / WS_) * RES_ + wx * WS_ + i % WS_;
            val = f2tf32(qkv0[((size_t)b * P_ + pos) * 384 + h * HD_ + d]);
        }
        q_s[i * 36 + d] = val;
    }
    __syncthreads();

    // ---- QK: M=64 N=128 K=32; warp tile 32x32 ----
    float cq[2][4][4];
    {
        const int wm = (warp & 1) * 32, wn = (warp >> 1) * 32;
#pragma unroll
        for (int mt = 0; mt < 2; mt++)
#pragma unroll
            for (int nt = 0; nt < 4; nt++)
#pragma unroll
                for (int f = 0; f < 4; f++) cq[mt][nt][f] = 0.f;

#pragma unroll
        for (int k8 = 0; k8 < 32; k8 += 8) {
            uint32_t a[2][4], bb[4][2];
#pragma unroll
            for (int mt = 0; mt < 2; mt++) {
                const int mrow = wm + mt * 16 + r;
                a[mt][0] = q_s[mrow * 36 + k8 + cI];
                a[mt][1] = q_s[(mrow + 8) * 36 + k8 + cI];
                a[mt][2] = q_s[mrow * 36 + k8 + cI + 4];
                a[mt][3] = q_s[(mrow + 8) * 36 + k8 + cI + 4];
            }
#pragma unroll
            for (int nt = 0; nt < 4; nt++) {
                const int nrow = wn + nt * 8 + r;
                bb[nt][0] = k_s[nrow * 36 + k8 + cI];
                bb[nt][1] = k_s[nrow * 36 + k8 + cI + 4];
            }
#pragma unroll
            for (int mt = 0; mt < 2; mt++)
#pragma unroll
                for (int nt = 0; nt < 4; nt++)
                    MMA_TF32(cq[mt][nt][0], cq[mt][nt][1], cq[mt][nt][2], cq[mt][nt][3],
                             a[mt][0], a[mt][1], a[mt][2], a[mt][3],
                             bb[nt][0], bb[nt][1]);
        }
    }

    // ---- issue V gather loads now (gmem; no smem dependence) ----
    float4 vv0, vv1, vv2, vv3;
    {
        const float4* vp = (const float4*)(basep + 2 * C_ + h * HD_ + half);
        vv0 = vp[0]; vv1 = vp[1]; vv2 = vp[2]; vv3 = vp[3];
    }
    __syncthreads();   // k_s and q_s now dead

    // ---- epilogue: store raw logits into p_s; write vT into k_s region ----
    {
        const int wm = (warp & 1) * 32, wn = (warp >> 1) * 32;
#pragma unroll
        for (int mt = 0; mt < 2; mt++) {
            const int row0 = wm + mt * 16 + r;
            const int row1 = row0 + 8;
#pragma unroll
            for (int nt = 0; nt < 4; nt++) {
                const int col = wn + nt * 8 + cI * 2;
                if (row0 < WA_) {
                    p_s[row0 * 132 + col]     = cq[mt][nt][0];
                    p_s[row0 * 132 + col + 1] = cq[mt][nt][1];
                }
                if (row1 < WA_) {
                    p_s[row1 * 132 + col]     = cq[mt][nt][2];
                    p_s[row1 * 132 + col + 1] = cq[mt][nt][3];
                }
            }
        }
        for (int idx = tid; idx < (64 - WA_) * 132; idx += 256)
            p_s[WA_ * 132 + idx] = 0.f;

        // transpose V into vT (aliased over k_s)
        const float vf[16] = {vv0.x, vv0.y, vv0.z, vv0.w,
                              vv1.x, vv1.y, vv1.z, vv1.w,
                              vv2.x, vv2.y, vv2.z, vv2.w,
                              vv3.x, vv3.y, vv3.z, vv3.w};
#pragma unroll
        for (int q = 0; q < 16; q++)
            vT_s[(half + q) * 132 + j] = f2tf32(vf[q]);
    }
    __syncthreads();

    // ---- softmax (fused scale + rpb, coalesced rpb reads) ----
    const float scale = 0.17677669529663687f;
    const float* rpb_wh = rpb + (size_t)(w * H_ + h) * WA_ * KV_;
    for (int i = warp; i < WA_; i += 8) {
        const float* rrow = rpb_wh + i * KV_;
        float x0 = fmaf(p_s[i * 132 + lane],      scale, rrow[lane]);
        float x1 = fmaf(p_s[i * 132 + lane + 32], scale, rrow[lane + 32]);
        float x2 = fmaf(p_s[i * 132 + lane + 64], scale, rrow[lane + 64]);
        float x3 = fmaf(p_s[i * 132 + lane + 96], scale, rrow[lane + 96]);
        float m = fmaxf(fmaxf(x0, x1), fmaxf(x2, x3));
#pragma unroll
        for (int off = 16; off; off >>= 1) m = fmaxf(m, __shfl_xor_sync(0xffffffffu, m, off));
        float e0 = __expf(x0 - m), e1 = __expf(x1 - m);
        float e2 = __expf(x2 - m), e3 = __expf(x3 - m);
        float s = e0 + e1 + e2 + e3;
#pragma unroll
        for (int off = 16; off; off >>= 1) s += __shfl_xor_sync(0xffffffffu, s, off);
        p_s[i * 132 + lane]      = e0;
        p_s[i * 132 + lane + 32] = e1;
        p_s[i * 132 + lane + 64] = e2;
        p_s[i * 132 + lane + 96] = e3;
        if (lane == 0) inv_s[i] = 1.f / s;
    }
    __syncthreads();

    // ---- PV: M=64 N=32 K=128; warp tile 16x16 ----
    {
        const int wm = (warp >> 1) * 16, wn = (warp & 1) * 16;
        float c[2][4];
#pragma unroll
        for (int nt = 0; nt < 2; nt++)
#pragma unroll
            for (int f = 0; f < 4; f++) c[nt][f] = 0.f;

        const int mrow = wm + r;
#pragma unroll
        for (int k8 = 0; k8 < KV_; k8 += 8) {
            uint32_t a0 = f2tf32(p_s[mrow * 132 + k8 + cI]);
            uint32_t a1 = f2tf32(p_s[(mrow + 8) * 132 + k8 + cI]);
            uint32_t a2 = f2tf32(p_s[mrow * 132 + k8 + cI + 4]);
            uint32_t a3 = f2tf32(p_s[(mrow + 8) * 132 + k8 + cI + 4]);
#pragma unroll
            for (int nt = 0; nt < 2; nt++) {
                const int nrow = wn + nt * 8 + r;
                uint32_t b0 = vT_s[nrow * 132 + k8 + cI];
                uint32_t b1 = vT_s[nrow * 132 + k8 + cI + 4];
                MMA_TF32(c[nt][0], c[nt][1], c[nt][2], c[nt][3],
                         a0, a1, a2, a3, b0, b1);
            }
        }

        const int row0 = wm + r, row1 = wm + r + 8;
#pragma unroll
        for (int nt = 0; nt < 2; nt++) {
            const int col = wn + nt * 8 + cI * 2;
            if (row0 < WA_) {
                float inv = inv_s[row0];
                float2 o = {c[nt][0] * inv, c[nt][1] * inv};
                *(float2*)&attn_out[(((size_t)(b * NQ_ + w) * WA_) + row0) * C_ + h * HD_ + col] = o;
            }
            if (row1 < WA_) {
                float inv = inv_s[row1];
                float2 o = {c[nt][2] * inv, c[nt][3] * inv};
                *(float2*)&attn_out[(((size_t)(b * NQ_ + w) * WA_) + row1) * C_ + h * HD_ + col] = o;
            }
        }
    }
}

// ============================================================
// launch
// ============================================================
extern "C" void kernel_launch(void* const* d_in, const int* in_sizes, int n_in,
                              void* d_out, int out_size)
{
    const float* x0      = (const float*)d_in[0];
    const float* x1      = (const float*)d_in[1];
    const float* qkv_w   = (const float*)d_in[2];
    const float* qkv_b   = (const float*)d_in[3];
    const float* proj_w  = (const float*)d_in[4];
    const float* proj_b  = (const float*)d_in[5];
    const float* rpb0_w1 = (const float*)d_in[6];
    const float* rpb0_b1 = (const float*)d_in[7];
    const float* rpb0_w2 = (const float*)d_in[8];
    const float* rpb0_b2 = (const float*)d_in[9];
    const float* rpb1_w1 = (const float*)d_in[10];
    const float* rpb1_b1 = (const float*)d_in[11];
    const float* rpb1_w2 = (const float*)d_in[12];
    const float* rpb1_b2 = (const float*)d_in[13];
    const float* coords0 = (const float*)d_in[14];
    const float* coords1 = (const float*)d_in[15];
    const int*   idx0    = (const int*)d_in[16];
    const int*   idx1    = (const int*)d_in[17];
    float* out = (float*)d_out;

    float *qkv0, *qkv1, *rpb, *attn_out;
    cudaGetSymbolAddress((void**)&qkv0, g_qkv0);
    cudaGetSymbolAddress((void**)&qkv1, g_qkv1);
    cudaGetSymbolAddress((void**)&rpb, g_rpb);
    cudaGetSymbolAddress((void**)&attn_out, g_attn_out);

    cudaFuncSetAttribute(attn_mma, cudaFuncAttributeMaxDynamicSharedMemorySize, SMEM_ATTN);

    gemm_tf32<<<dim3(M0_ / 128, 384 / 128), 256>>>(x0, qkv_w, qkv_b, qkv0, M0_, 384, 128);
    gemm_tf32<<<dim3(M1_ / 128, 384 / 128), 256>>>(x1, qkv_w, qkv_b, qkv1, M1_, 384, 128);
    rpb_kernel<<<(NQ_ * WA_ * KV_ + 255) / 256, 256>>>(
        coords0, coords1,
        rpb0_w1, rpb0_b1, rpb0_w2, rpb0_b2,
        rpb1_w1, rpb1_b1, rpb1_w2, rpb1_b2, rpb);
    attn_mma<<<dim3(NQ_, B_, H_), 256, SMEM_ATTN>>>(idx0, idx1, rpb, qkv0, qkv1, attn_out);
    gemm_tf32<<<dim3(M0_ / 128, C_ / 128), 256>>>(attn_out, proj_w, proj_b, out, M0_, C_, 128);
}

// round 6
// speedup vs baseline: 2.3782x; 1.0322x over previous
#include <cuda_runtime.h>
#include <cuda_bf16.h>
#include <cstdint>
#include <cstring>

#define B_   32
#define RES_ 56
#define C_   128
#define H_   4
#define HD_  32
#define WS_  7
#define NW_  8
#define NQ_  64
#define WA_  49
#define TOPK_ 64
#define KV_  128
#define P_   3136
#define M0_  (B_*P_)
#define M1_  (B_*NQ_)

__device__ float g_qkv0[(size_t)M0_ * 384];
__device__ float g_qkv1[(size_t)M1_ * 384];
__device__ float g_rpb[(size_t)NQ_ * H_ * WA_ * KV_];
__device__ float g_attn_out[(size_t)M0_ * C_];

__device__ __forceinline__ uint32_t f2tf32(float f) {
    uint32_t r;
    asm("cvt.rna.tf32.f32 %0, %1;" : "=r"(r) : "f"(f));
    return r;
}
__device__ __forceinline__ uint4 cvt4(float4 v) {
    uint4 u = {f2tf32(v.x), f2tf32(v.y), f2tf32(v.z), f2tf32(v.w)};
    return u;
}

#define MMA_TF32(C0,C1,C2,C3,A0,A1,A2,A3,B0,B1) \
    asm volatile("mma.sync.aligned.m16n8k8.row.col.f32.tf32.tf32.f32 " \
        "{%0,%1,%2,%3},{%4,%5,%6,%7},{%8,%9},{%0,%1,%2,%3};" \
        : "+f"(C0), "+f"(C1), "+f"(C2), "+f"(C3) \
        : "r"(A0), "r"(A1), "r"(A2), "r"(A3), "r"(B0), "r"(B1))

// ============================================================
// TF32 GEMM: C[M,N] = A[M,K]*B[N,K]^T + bias[N]; BK=32,
// register double-buffered global loads.
// ============================================================
__global__ __launch_bounds__(256) void gemm_tf32(
    const float* __restrict__ A, const float* __restrict__ Bm,
    const float* __restrict__ bias, float* __restrict__ C,
    int M, int N, int K)
{
    __shared__ uint32_t As[128][36];
    __shared__ uint32_t Bs[128][36];

    const int tid = threadIdx.x;
    const int m0 = blockIdx.x * 128;
    const int n0 = blockIdx.y * 128;
    const int warp = tid >> 5, lane = tid & 31;
    const int wm = (warp >> 2) * 64;
    const int wn = (warp & 3) * 32;
    const int r = lane >> 2;
    const int cI = lane & 3;

    float c[4][4][4];
#pragma unroll
    for (int mt = 0; mt < 4; mt++)
#pragma unroll
        for (int nt = 0; nt < 4; nt++)
#pragma unroll
            for (int f = 0; f < 4; f++) c[mt][nt][f] = 0.f;

    const int lr = tid >> 1;
    const int ls = (tid & 1) * 16;
    const float* Arow = A + (size_t)(m0 + lr) * K + ls;
    const float* Brow = Bm + (size_t)(n0 + lr) * K + ls;

    float4 ra[4], rb[4];
#pragma unroll
    for (int q = 0; q < 4; q++) {
        ra[q] = *(const float4*)(Arow + q * 4);
        rb[q] = *(const float4*)(Brow + q * 4);
    }

    for (int k0 = 0; k0 < K; k0 += 32) {
#pragma unroll
        for (int q = 0; q < 4; q++) {
            *(uint4*)&As[lr][ls + q * 4] = cvt4(ra[q]);
            *(uint4*)&Bs[lr][ls + q * 4] = cvt4(rb[q]);
        }
        __syncthreads();

        if (k0 + 32 < K) {
#pragma unroll
            for (int q = 0; q < 4; q++) {
                ra[q] = *(const float4*)(Arow + k0 + 32 + q * 4);
                rb[q] = *(const float4*)(Brow + k0 + 32 + q * 4);
            }
        }

#pragma unroll
        for (int k8 = 0; k8 < 32; k8 += 8) {
            uint32_t a[4][4], b[4][2];
#pragma unroll
            for (int mt = 0; mt < 4; mt++) {
                const int mrow = wm + mt * 16 + r;
                a[mt][0] = As[mrow][k8 + cI];
                a[mt][1] = As[mrow + 8][k8 + cI];
                a[mt][2] = As[mrow][k8 + cI + 4];
                a[mt][3] = As[mrow + 8][k8 + cI + 4];
            }
#pragma unroll
            for (int nt = 0; nt < 4; nt++) {
                const int nrow = wn + nt * 8 + r;
                b[nt][0] = Bs[nrow][k8 + cI];
                b[nt][1] = Bs[nrow][k8 + cI + 4];
            }
#pragma unroll
            for (int mt = 0; mt < 4; mt++)
#pragma unroll
                for (int nt = 0; nt < 4; nt++)
                    MMA_TF32(c[mt][nt][0], c[mt][nt][1], c[mt][nt][2], c[mt][nt][3],
                             a[mt][0], a[mt][1], a[mt][2], a[mt][3],
                             b[nt][0], b[nt][1]);
        }
        __syncthreads();
    }

#pragma unroll
    for (int mt = 0; mt < 4; mt++) {
        const int row = m0 + wm + mt * 16 + r;
#pragma unroll
        for (int nt = 0; nt < 4; nt++) {
            const int col = n0 + wn + nt * 8 + cI * 2;
            float2 bb = *(const float2*)&bias[col];
            float2 o0 = {c[mt][nt][0] + bb.x, c[mt][nt][1] + bb.y};
            float2 o1 = {c[mt][nt][2] + bb.x, c[mt][nt][3] + bb.y};
            *(float2*)&C[(size_t)row * N + col]       = o0;
            *(float2*)&C[(size_t)(row + 8) * N + col] = o1;
        }
    }
}

// ============================================================
// RPB MLP precompute
// ============================================================
__global__ void rpb_kernel(
    const float* __restrict__ coords0, const float* __restrict__ coords1,
    const float* __restrict__ w1a, const float* __restrict__ b1a,
    const float* __restrict__ w2a, const float* __restrict__ b2a,
    const float* __restrict__ w1b, const float* __restrict__ b1b,
    const float* __restrict__ w2b, const float* __restrict__ b2b,
    float* __restrict__ rpb)
{
    int t = blockIdx.x * blockDim.x + threadIdx.x;
    const int TOT = NQ_ * WA_ * KV_;
    if (t >= TOT) return;
    int j = t & 127;
    int i = (t >> 7) % WA_;
    int w = t / (KV_ * WA_);

    const float *co, *w1, *b1, *w2, *b2;
    int jj;
    if (j < TOPK_) { co = coords0; jj = j;          w1 = w1a; b1 = b1a; w2 = w2a; b2 = b2a; }
    else           { co = coords1; jj = j - TOPK_;  w1 = w1b; b1 = b1b; w2 = w2b; b2 = b2b; }

    size_t cbase = ((size_t)(w * WA_ + i) * TOPK_ + jj) * 2;
    float cy = co[cbase + 0];
    float cx = co[cbase + 1];

    float o0 = b2[0], o1 = b2[1], o2 = b2[2], o3 = b2[3];
#pragma unroll
    for (int tt = 0; tt < HD_; tt++) {
        float hsum = fmaxf(fmaf(w1[tt * 2], cy, fmaf(w1[tt * 2 + 1], cx, b1[tt])), 0.f);
        o0 = fmaf(w2[0 * HD_ + tt], hsum, o0);
        o1 = fmaf(w2[1 * HD_ + tt], hsum, o1);
        o2 = fmaf(w2[2 * HD_ + tt], hsum, o2);
        o3 = fmaf(w2[3 * HD_ + tt], hsum, o3);
    }
    size_t base = ((size_t)(w * H_) * WA_ + i) * KV_ + j;
    const size_t hstride = (size_t)WA_ * KV_;
    rpb[base + 0 * hstride] = o0;
    rpb[base + 1 * hstride] = o1;
    rpb[base + 2 * hstride] = o2;
    rpb[base + 3 * hstride] = o3;
}

// ============================================================
// Tensor-core attention (smem 52480 B, 4 CTAs/SM)
// ============================================================
#define SMEM_ATTN 52480

__global__ __launch_bounds__(256, 4) void attn_mma(
    const int* __restrict__ idx0, const int* __restrict__ idx1,
    const float* __restrict__ rpb,
    const float* __restrict__ qkv0, const float* __restrict__ qkv1,
    float* __restrict__ attn_out)
{
    extern __shared__ char smem_raw[];
    uint32_t* k_s  = (uint32_t*)(smem_raw);            // phase 1
    uint32_t* vT_s = (uint32_t*)(smem_raw);            // phase 2 alias
    float*    p_s  = (float*)   (smem_raw + 18432);
    uint32_t* p_u  = (uint32_t*)(smem_raw + 18432);    // tf32 view after softmax
    uint32_t* q_s  = (uint32_t*)(smem_raw + 18432);    // alias (dead after QK)
    float*    inv_s= (float*)   (smem_raw + 52224);

    const int w = blockIdx.x, b = blockIdx.y, h = blockIdx.z;
    const int tid = threadIdx.x;
    const int warp = tid >> 5, lane = tid & 31;
    const int r = lane >> 2, cI = lane & 3;

    // ---- gather K: 2 threads per key row ----
    const int j = tid >> 1;
    const int half = (tid & 1) * 16;
    const float* basep;
    if (j < TOPK_) basep = qkv0 + ((size_t)b * P_ + idx0[w * TOPK_ + j]) * 384;
    else           basep = qkv1 + ((size_t)b * NQ_ + idx1[w * TOPK_ + (j - TOPK_)]) * 384;

    {
        const float4* kp = (const float4*)(basep + C_ + h * HD_ + half);
#pragma unroll
        for (int t4 = 0; t4 < 4; t4++)
            *(uint4*)&k_s[j * 36 + half + t4 * 4] = cvt4(kp[t4]);
    }

    // ---- load Q (49 rows, pad to 64 with zeros) ----
    const int wy = w >> 3, wx = w & 7;
    for (int idx = tid; idx < 64 * HD_; idx += 256) {
        int i = idx >> 5, d = idx & 31;
        uint32_t val = 0u;
        if (i < WA_) {
            int pos = (wy * WS_ + i / WS_) * RES_ + wx * WS_ + i % WS_;
            val = f2tf32(qkv0[((size_t)b * P_ + pos) * 384 + h * HD_ + d]);
        }
        q_s[i * 36 + d] = val;
    }
    __syncthreads();

    // ---- QK: M=64 N=128 K=32 ----
    float cq[2][4][4];
    {
        const int wm = (warp & 1) * 32, wn = (warp >> 1) * 32;
#pragma unroll
        for (int mt = 0; mt < 2; mt++)
#pragma unroll
            for (int nt = 0; nt < 4; nt++)
#pragma unroll
                for (int f = 0; f < 4; f++) cq[mt][nt][f] = 0.f;

#pragma unroll
        for (int k8 = 0; k8 < 32; k8 += 8) {
            uint32_t a[2][4], bb[4][2];
#pragma unroll
            for (int mt = 0; mt < 2; mt++) {
                const int mrow = wm + mt * 16 + r;
                a[mt][0] = q_s[mrow * 36 + k8 + cI];
                a[mt][1] = q_s[(mrow + 8) * 36 + k8 + cI];
                a[mt][2] = q_s[mrow * 36 + k8 + cI + 4];
                a[mt][3] = q_s[(mrow + 8) * 36 + k8 + cI + 4];
            }
#pragma unroll
            for (int nt = 0; nt < 4; nt++) {
                const int nrow = wn + nt * 8 + r;
                bb[nt][0] = k_s[nrow * 36 + k8 + cI];
                bb[nt][1] = k_s[nrow * 36 + k8 + cI + 4];
            }
#pragma unroll
            for (int mt = 0; mt < 2; mt++)
#pragma unroll
                for (int nt = 0; nt < 4; nt++)
                    MMA_TF32(cq[mt][nt][0], cq[mt][nt][1], cq[mt][nt][2], cq[mt][nt][3],
                             a[mt][0], a[mt][1], a[mt][2], a[mt][3],
                             bb[nt][0], bb[nt][1]);
        }
    }

    // ---- issue V gather loads (no smem dependence) ----
    float4 vv0, vv1, vv2, vv3;
    {
        const float4* vp = (const float4*)(basep + 2 * C_ + h * HD_ + half);
        vv0 = vp[0]; vv1 = vp[1]; vv2 = vp[2]; vv3 = vp[3];
    }
    __syncthreads();

    // ---- epilogue: raw logits -> p_s; transpose V -> vT ----
    {
        const int wm = (warp & 1) * 32, wn = (warp >> 1) * 32;
#pragma unroll
        for (int mt = 0; mt < 2; mt++) {
            const int row0 = wm + mt * 16 + r;
            const int row1 = row0 + 8;
#pragma unroll
            for (int nt = 0; nt < 4; nt++) {
                const int col = wn + nt * 8 + cI * 2;
                if (row0 < WA_) {
                    p_s[row0 * 132 + col]     = cq[mt][nt][0];
                    p_s[row0 * 132 + col + 1] = cq[mt][nt][1];
                }
                if (row1 < WA_) {
                    p_s[row1 * 132 + col]     = cq[mt][nt][2];
                    p_s[row1 * 132 + col + 1] = cq[mt][nt][3];
                }
            }
        }
        for (int idx = tid; idx < (64 - WA_) * 132; idx += 256)
            p_u[WA_ * 132 + idx] = 0u;

        const float vf[16] = {vv0.x, vv0.y, vv0.z, vv0.w,
                              vv1.x, vv1.y, vv1.z, vv1.w,
                              vv2.x, vv2.y, vv2.z, vv2.w,
                              vv3.x, vv3.y, vv3.z, vv3.w};
#pragma unroll
        for (int q = 0; q < 16; q++)
            vT_s[(half + q) * 132 + j] = f2tf32(vf[q]);
    }
    __syncthreads();

    // ---- softmax (fused scale + rpb); store exp pre-converted to tf32 ----
    const float scale = 0.17677669529663687f;
    const float* rpb_wh = rpb + (size_t)(w * H_ + h) * WA_ * KV_;
    for (int i = warp; i < WA_; i += 8) {
        const float* rrow = rpb_wh + i * KV_;
        float x0 = fmaf(p_s[i * 132 + lane],      scale, rrow[lane]);
        float x1 = fmaf(p_s[i * 132 + lane + 32], scale, rrow[lane + 32]);
        float x2 = fmaf(p_s[i * 132 + lane + 64], scale, rrow[lane + 64]);
        float x3 = fmaf(p_s[i * 132 + lane + 96], scale, rrow[lane + 96]);
        float m = fmaxf(fmaxf(x0, x1), fmaxf(x2, x3));
#pragma unroll
        for (int off = 16; off; off >>= 1) m = fmaxf(m, __shfl_xor_sync(0xffffffffu, m, off));
        float e0 = __expf(x0 - m), e1 = __expf(x1 - m);
        float e2 = __expf(x2 - m), e3 = __expf(x3 - m);
        float s = e0 + e1 + e2 + e3;
#pragma unroll
        for (int off = 16; off; off >>= 1) s += __shfl_xor_sync(0xffffffffu, s, off);
        p_u[i * 132 + lane]      = f2tf32(e0);
        p_u[i * 132 + lane + 32] = f2tf32(e1);
        p_u[i * 132 + lane + 64] = f2tf32(e2);
        p_u[i * 132 + lane + 96] = f2tf32(e3);
        if (lane == 0) inv_s[i] = 1.f / s;
    }
    __syncthreads();

    // ---- PV: M=64 N=32 K=128 (A already tf32 in smem) ----
    {
        const int wm = (warp >> 1) * 16, wn = (warp & 1) * 16;
        float c[2][4];
#pragma unroll
        for (int nt = 0; nt < 2; nt++)
#pragma unroll
            for (int f = 0; f < 4; f++) c[nt][f] = 0.f;

        const int mrow = wm + r;
#pragma unroll
        for (int k8 = 0; k8 < KV_; k8 += 8) {
            uint32_t a0 = p_u[mrow * 132 + k8 + cI];
            uint32_t a1 = p_u[(mrow + 8) * 132 + k8 + cI];
            uint32_t a2 = p_u[mrow * 132 + k8 + cI + 4];
            uint32_t a3 = p_u[(mrow + 8) * 132 + k8 + cI + 4];
#pragma unroll
            for (int nt = 0; nt < 2; nt++) {
                const int nrow = wn + nt * 8 + r;
                uint32_t b0 = vT_s[nrow * 132 + k8 + cI];
                uint32_t b1 = vT_s[nrow * 132 + k8 + cI + 4];
                MMA_TF32(c[nt][0], c[nt][1], c[nt][2], c[nt][3],
                         a0, a1, a2, a3, b0, b1);
            }
        }

        const int row0 = wm + r, row1 = wm + r + 8;
#pragma unroll
        for (int nt = 0; nt < 2; nt++) {
            const int col = wn + nt * 8 + cI * 2;
            if (row0 < WA_) {
                float inv = inv_s[row0];
                float2 o = {c[nt][0] * inv, c[nt][1] * inv};
                *(float2*)&attn_out[(((size_t)(b * NQ_ + w) * WA_) + row0) * C_ + h * HD_ + col] = o;
            }
            if (row1 < WA_) {
                float inv = inv_s[row1];
                float2 o = {c[nt][2] * inv, c[nt][3] * inv};
                *(float2*)&attn_out[(((size_t)(b * NQ_ + w) * WA_) + row1) * C_ + h * HD_ + col] = o;
            }
        }
    }
}

// ============================================================
// launch
// ============================================================
extern "C" void kernel_launch(void* const* d_in, const int* in_sizes, int n_in,
                              void* d_out, int out_size)
{
    const float* x0      = (const float*)d_in[0];
    const float* x1      = (const float*)d_in[1];
    const float* qkv_w   = (const float*)d_in[2];
    const float* qkv_b   = (const float*)d_in[3];
    const float* proj_w  = (const float*)d_in[4];
    const float* proj_b  = (const float*)d_in[5];
    const float* rpb0_w1 = (const float*)d_in[6];
    const float* rpb0_b1 = (const float*)d_in[7];
    const float* rpb0_w2 = (const float*)d_in[8];
    const float* rpb0_b2 = (const float*)d_in[9];
    const float* rpb1_w1 = (const float*)d_in[10];
    const float* rpb1_b1 = (const float*)d_in[11];
    const float* rpb1_w2 = (const float*)d_in[12];
    const float* rpb1_b2 = (const float*)d_in[13];
    const float* coords0 = (const float*)d_in[14];
    const float* coords1 = (const float*)d_in[15];
    const int*   idx0    = (const int*)d_in[16];
    const int*   idx1    = (const int*)d_in[17];
    float* out = (float*)d_out;

    float *qkv0, *qkv1, *rpb, *attn_out;
    cudaGetSymbolAddress((void**)&qkv0, g_qkv0);
    cudaGetSymbolAddress((void**)&qkv1, g_qkv1);
    cudaGetSymbolAddress((void**)&rpb, g_rpb);
    cudaGetSymbolAddress((void**)&attn_out, g_attn_out);

    cudaFuncSetAttribute(attn_mma, cudaFuncAttributeMaxDynamicSharedMemorySize, SMEM_ATTN);

    gemm_tf32<<<dim3(M0_ / 128, 384 / 128), 256>>>(x0, qkv_w, qkv_b, qkv0, M0_, 384, 128);
    gemm_tf32<<<dim3(M1_ / 128, 384 / 128), 256>>>(x1, qkv_w, qkv_b, qkv1, M1_, 384, 128);
    rpb_kernel<<<(NQ_ * WA_ * KV_ + 255) / 256, 256>>>(
        coords0, coords1,
        rpb0_w1, rpb0_b1, rpb0_w2, rpb0_b2,
        rpb1_w1, rpb1_b1, rpb1_w2, rpb1_b2, rpb);
    attn_mma<<<dim3(NQ_, B_, H_), 256, SMEM_ATTN>>>(idx0, idx1, rpb, qkv0, qkv1, attn_out);
    gemm_tf32<<<dim3(M0_ / 128, C_ / 128), 256>>>(attn_out, proj_w, proj_b, out, M0_, C_, 128);
}